// round 12
// baseline (speedup 1.0000x reference)
#include <cuda_runtime.h>
#include <cuda_bf16.h>
#include <cstdint>

// ---------------------------------------------------------------------------
// Swin Transformer block, bf16 mma.sync m16n8k16 GEMMs (ldmatrix fragments),
// 256x128 CTA tile, cp.async 3-stage, 2 CTAs/SM.
// B=16, H=W=64, C=512, NH=4, WS=8, SS=4
// ---------------------------------------------------------------------------

#define TOKENS   65536
#define DIMC     512
#define NWIN     1024

// scratch layout (float-indexed offsets; bf16 regions reinterpret, use <= half)
#define OFF_HW     0L
#define OFF_QKV    33554432L
#define OFF_AOUT   134217728L
#define OFF_X2     167772160L
#define OFF_H2N    201326592L
#define OFF_MLP1   234881024L
#define OFF_WQKV   369098752L      // transposed bf16 weights [N][K]
#define OFF_WPROJ  369885184L
#define OFF_WM1    370147328L
#define OFF_WM2    371195904L
#define SCRATCH_FLOATS 372244480L

__device__ float g_scratch[SCRATCH_FLOATS];

// ---------------- helpers ----------------
__device__ __forceinline__ uint32_t smem_u32(const void* p) {
    uint32_t a;
    asm("{ .reg .u64 t; cvta.to.shared.u64 t, %1; cvt.u32.u64 %0, t; }" : "=r"(a) : "l"(p));
    return a;
}
__device__ __forceinline__ void cp_async16(uint32_t dst, const void* src) {
    asm volatile("cp.async.cg.shared.global [%0], [%1], 16;" :: "r"(dst), "l"(src));
}
__device__ __forceinline__ void ldsm_x4(uint32_t& r0, uint32_t& r1, uint32_t& r2,
                                        uint32_t& r3, uint32_t addr) {
    asm volatile("ldmatrix.sync.aligned.m8n8.x4.shared.b16 {%0,%1,%2,%3}, [%4];"
                 : "=r"(r0), "=r"(r1), "=r"(r2), "=r"(r3) : "r"(addr));
}
__device__ __forceinline__ void mma_bf16(float* d, const uint32_t* a, const uint32_t* b) {
    asm volatile(
        "mma.sync.aligned.m16n8k16.row.col.f32.bf16.bf16.f32 "
        "{%0,%1,%2,%3}, {%4,%5,%6,%7}, {%8,%9}, {%0,%1,%2,%3};"
        : "+f"(d[0]), "+f"(d[1]), "+f"(d[2]), "+f"(d[3])
        : "r"(a[0]), "r"(a[1]), "r"(a[2]), "r"(a[3]), "r"(b[0]), "r"(b[1]));
}
__device__ __forceinline__ uint32_t pack_bf2(float x, float y) {
    __nv_bfloat162 p = __float22bfloat162_rn(make_float2(x, y));
    return *(uint32_t*)&p;
}

// ---------------------------------------------------------------------------
// Weight transpose [K,N] -> [N,K], bf16
// ---------------------------------------------------------------------------
__global__ __launch_bounds__(256) void transpose_kernel(
    const float* __restrict__ W, __nv_bfloat16* __restrict__ Wt, int K, int N)
{
    __shared__ float t[32][33];
    int n0 = blockIdx.x * 32, k0 = blockIdx.y * 32;
#pragma unroll
    for (int i = threadIdx.y; i < 32; i += 8)
        t[i][threadIdx.x] = W[(long)(k0 + i) * N + n0 + threadIdx.x];
    __syncthreads();
#pragma unroll
    for (int i = threadIdx.y; i < 32; i += 8)
        Wt[(long)(n0 + i) * K + k0 + threadIdx.x] = __float2bfloat16_rn(t[threadIdx.x][i]);
}

// ---------------------------------------------------------------------------
// LayerNorm (+ optional shift & window partition of SOURCE row), bf16 output
// ---------------------------------------------------------------------------
__global__ __launch_bounds__(128) void ln_kernel(
    const float* __restrict__ src, const float* __restrict__ gamma,
    const float* __restrict__ beta, __nv_bfloat16* __restrict__ dst, int do_shift)
{
    int r = blockIdx.x;
    long srow = r;
    if (do_shift) {
        int wi = r >> 6, n = r & 63;
        int b  = wi >> 6, wrem = wi & 63;
        int wy = wrem >> 3, wx = wrem & 7;
        int iy = n >> 3,   ix = n & 7;
        int h = (wy * 8 + iy + 4) & 63;
        int w = (wx * 8 + ix + 4) & 63;
        srow = ((long)b * 64 + h) * 64 + w;
    }
    int c = threadIdx.x * 4;
    float4 v = *(const float4*)(src + srow * DIMC + c);
    float s  = v.x + v.y + v.z + v.w;
    float ss = v.x * v.x + v.y * v.y + v.z * v.z + v.w * v.w;
#pragma unroll
    for (int o = 16; o; o >>= 1) {
        s  += __shfl_xor_sync(0xffffffffu, s,  o);
        ss += __shfl_xor_sync(0xffffffffu, ss, o);
    }
    __shared__ float red[8];
    int warp = threadIdx.x >> 5, lane = threadIdx.x & 31;
    if (lane == 0) { red[warp] = s; red[warp + 4] = ss; }
    __syncthreads();
    s  = red[0] + red[1] + red[2] + red[3];
    ss = red[4] + red[5] + red[6] + red[7];
    float mean = s * (1.0f / 512.0f);
    float var  = ss * (1.0f / 512.0f) - mean * mean;
    float inv  = rsqrtf(var + 1e-5f);
    float4 g4 = *(const float4*)(gamma + c);
    float4 b4 = *(const float4*)(beta + c);
    uint2 pk;
    pk.x = pack_bf2((v.x - mean) * inv * g4.x + b4.x, (v.y - mean) * inv * g4.y + b4.y);
    pk.y = pack_bf2((v.z - mean) * inv * g4.z + b4.z, (v.w - mean) * inv * g4.w + b4.w);
    *(uint2*)(dst + (long)r * DIMC + c) = pk;
}

// ---------------------------------------------------------------------------
// bf16 mma GEMM: C[M,N] = A[M,K] @ Wt[N,K]^T   (A, Wt bf16; acc fp32)
// CTA tile 256x128, BK=32 halves, 3-stage cp.async, 2 CTAs/SM,
// 8 warps (4m x 2n), warp tile 64x64: per chunk 2 x (8 ldsm.x4 + 32 mma).
// smem stride 40 halves (80B) -> conflict-free ldmatrix rows.
// Loader: ar=tid>>2 (0..63), ac=(tid&3)*8 (0..24) halves; A 4 iters, B 2.
// Epilogue: regs -> smem staging[256][68] (fp32) -> fused writeout.
// modes: 0 bias(f32 out) | 1 bias+winrev+residual(f32) | 2 bias+GELU(bf16 out)
//        | 3 bias+residual(f32)
// ---------------------------------------------------------------------------
#define LDH 40
#define A_HALVES (256 * LDH)                       // 10240
#define STAGE_HALVES (256 * LDH + 128 * LDH)       // 15360 (30720 B)
#define NSTAGE 3
#define GSMEM_BYTES (NSTAGE * STAGE_HALVES * 2)    // 92160
#define LDS 68

__global__ __launch_bounds__(256, 2) void mma_gemm(
    const __nv_bfloat16* __restrict__ A, const __nv_bfloat16* __restrict__ Wt,
    const float* __restrict__ bias, void* __restrict__ Cv,
    int K, int N, int mode, const float* __restrict__ res)
{
    extern __shared__ __align__(16) float sraw[];
    const uint32_t sb = smem_u32(sraw);

    const int tid  = threadIdx.x;
    const int lane = tid & 31;
    const int warp = tid >> 5;
    const int wm   = warp & 3;    // 0..3 -> 64-row slab
    const int wn   = warp >> 2;   // 0..1 -> 64-col slab
    const long brow = (long)blockIdx.y * 256;
    const int  bcol = blockIdx.x * 128;
    const int  Cn = K >> 5;

    // global->smem geometry: 16B (8 halves) per cp; chunk = 32 halves/row
    const int ar = tid >> 2;             // 0..63
    const int ac = (tid & 3) << 3;       // 0,8,16,24 halves

    auto issue_load = [&](int c, int s) {
        const int k0 = c * 32;                       // halves
        const uint32_t as = sb + (uint32_t)(s * STAGE_HALVES) * 2;
        const uint32_t bs = as + A_HALVES * 2;
#pragma unroll
        for (int i = 0; i < 4; i++) {
            int r = ar + i * 64;
            cp_async16(as + (r * LDH + ac) * 2, A + (brow + r) * (long)K + k0 + ac);
        }
#pragma unroll
        for (int i = 0; i < 2; i++) {
            int r = ar + i * 64;
            cp_async16(bs + (r * LDH + ac) * 2, Wt + (long)(bcol + r) * K + k0 + ac);
        }
        asm volatile("cp.async.commit_group;" ::: "memory");
    };

    float acc[4][8][4];
#pragma unroll
    for (int mt = 0; mt < 4; mt++)
#pragma unroll
        for (int nt = 0; nt < 8; nt++)
#pragma unroll
            for (int q = 0; q < 4; q++) acc[mt][nt][q] = 0.0f;

    // ldmatrix per-lane geometry
    const int lrow = (lane & 7) + ((lane >> 3) & 1) * 8;   // 0..15
    const int lcol = (lane >> 4) * 8;                       // halves: 0 or 8

    issue_load(0, 0);
    issue_load(1, 1);

    for (int c = 0; c < Cn; c++) {
        asm volatile("cp.async.wait_group 1;" ::: "memory");
        __syncthreads();
        if (c + NSTAGE - 1 < Cn) issue_load(c + NSTAGE - 1, (c + NSTAGE - 1) % NSTAGE);
        else asm volatile("cp.async.commit_group;" ::: "memory");

        const uint32_t stage = sb + (uint32_t)((c % NSTAGE) * STAGE_HALVES) * 2;
        const uint32_t a_off = stage + ((wm * 64 + lrow) * LDH + lcol) * 2;
        const uint32_t b_off = stage + A_HALVES * 2 + ((wn * 64 + lrow) * LDH + lcol) * 2;
#pragma unroll
        for (int ks = 0; ks < 2; ks++) {
            uint32_t af[4][4], bf[8][2];
#pragma unroll
            for (int mt = 0; mt < 4; mt++)
                ldsm_x4(af[mt][0], af[mt][1], af[mt][2], af[mt][3],
                        a_off + (mt * 16 * LDH + ks * 16) * 2);
#pragma unroll
            for (int np = 0; np < 4; np++) {
                uint32_t r0, r1, r2, r3;
                ldsm_x4(r0, r1, r2, r3, b_off + (np * 16 * LDH + ks * 16) * 2);
                bf[2 * np][0] = r0; bf[2 * np][1] = r2;
                bf[2 * np + 1][0] = r1; bf[2 * np + 1][1] = r3;
            }
#pragma unroll
            for (int mt = 0; mt < 4; mt++)
#pragma unroll
                for (int nt = 0; nt < 8; nt++)
                    mma_bf16(acc[mt][nt], af[mt], bf[nt]);
        }
    }
    asm volatile("cp.async.wait_group 0;" ::: "memory");

    // ---------------- epilogue: two 64-column passes via shared staging ----
    const int gr  = lane >> 2;
    const int tg2 = (lane & 3) * 2;
#pragma unroll 1
    for (int pass = 0; pass < 2; pass++) {
        __syncthreads();
        if (wn == pass) {
#pragma unroll
            for (int mt = 0; mt < 4; mt++)
#pragma unroll
                for (int nt = 0; nt < 8; nt++) {
                    float* st = sraw + (wm * 64 + mt * 16 + gr) * LDS + nt * 8 + tg2;
                    *(float2*)st = make_float2(acc[mt][nt][0], acc[mt][nt][1]);
                    *(float2*)(st + 8 * LDS) = make_float2(acc[mt][nt][2], acc[mt][nt][3]);
                }
        }
        __syncthreads();

        const int r = tid;           // 256 rows, one per thread
        long rr = brow + r;
        long orow = rr;
        if (mode == 1) {
            int ri = (int)rr;
            int wi = ri >> 6, n = ri & 63;
            int b  = wi >> 6, wrem = wi & 63;
            int wy = wrem >> 3, wx = wrem & 7;
            int iy = n >> 3,   ix = n & 7;
            int h = (wy * 8 + iy + 4) & 63;
            int w = (wx * 8 + ix + 4) & 63;
            orow = ((long)b * 64 + h) * 64 + w;
        }
        float* crow = (mode == 2) ? nullptr : (float*)Cv + orow * (long)N;
        __nv_bfloat16* crow_bf = (mode == 2)
            ? (__nv_bfloat16*)Cv + orow * (long)N : nullptr;
        const float* rrow = (mode == 1 || mode == 3) ? res + orow * (long)N : nullptr;
#pragma unroll
        for (int j = 0; j < 64; j += 4) {
            int col = bcol + pass * 64 + j;
            float4 v = *(const float4*)(sraw + r * LDS + j);
            float4 b4 = *(const float4*)(bias + col);
            v.x += b4.x; v.y += b4.y; v.z += b4.z; v.w += b4.w;
            if (mode == 2) {
                v.x = 0.5f * v.x * (1.0f + erff(v.x * 0.70710678118654752f));
                v.y = 0.5f * v.y * (1.0f + erff(v.y * 0.70710678118654752f));
                v.z = 0.5f * v.z * (1.0f + erff(v.z * 0.70710678118654752f));
                v.w = 0.5f * v.w * (1.0f + erff(v.w * 0.70710678118654752f));
                uint2 pk;
                pk.x = pack_bf2(v.x, v.y);
                pk.y = pack_bf2(v.z, v.w);
                *(uint2*)(crow_bf + col) = pk;
            } else {
                if (rrow) {
                    float4 r4 = *(const float4*)(rrow + col);
                    v.x += r4.x; v.y += r4.y; v.z += r4.z; v.w += r4.w;
                }
                *(float4*)(crow + col) = v;
            }
        }
    }
}

// ---------------------------------------------------------------------------
// Windowed attention (SIMT fp32 / f32x2), bf16 output
// ---------------------------------------------------------------------------
__device__ __forceinline__ unsigned long long splat2(float x) {
    unsigned long long r; unsigned u = __float_as_uint(x);
    asm("mov.b64 %0, {%1, %1};" : "=l"(r) : "r"(u));
    return r;
}
__device__ __forceinline__ void unpack2(unsigned long long v, float& lo, float& hi) {
    unsigned a, b;
    asm("mov.b64 {%0, %1}, %2;" : "=r"(a), "=r"(b) : "l"(v));
    lo = __uint_as_float(a); hi = __uint_as_float(b);
}
__device__ __forceinline__ void fma2(unsigned long long& d, unsigned long long a,
                                     unsigned long long b) {
    asm("fma.rn.f32x2 %0, %1, %2, %0;" : "+l"(d) : "l"(a), "l"(b));
}

#define ATTN_SMEM_FLOATS (64*132 + 128*66 + 64*132 + 64*65 + 240)
#define ATTN_SMEM_BYTES  (ATTN_SMEM_FLOATS * 4)

__global__ __launch_bounds__(256, 1) void attn_kernel(
    const float* __restrict__ qkv, const float* __restrict__ bias_table,
    __nv_bfloat16* __restrict__ out)
{
    extern __shared__ float sm[];
    float* qs = sm;
    float* kt = qs + 64 * 132;
    float* vs = kt + 128 * 66;
    float* at = vs + 64 * 132;
    float* bt = at + 64 * 65;

    const int wi   = blockIdx.x >> 2;
    const int head = blockIdx.x & 3;
    const int tid  = threadIdx.x;
    const float SCALE = 0.08838834764831845f;

    const float* base = qkv + (long)wi * 64 * 1536 + head * 128;
    for (int idx = tid; idx < 64 * 32; idx += 256) {
        int row = idx >> 5;
        int c   = (idx & 31) << 2;
        const float* p = base + (long)row * 1536 + c;
        float4 q4 = *(const float4*)(p);
        float4 k4 = *(const float4*)(p + 512);
        float4 v4 = *(const float4*)(p + 1024);
        qs[row * 132 + c + 0] = q4.x * SCALE;
        qs[row * 132 + c + 1] = q4.y * SCALE;
        qs[row * 132 + c + 2] = q4.z * SCALE;
        qs[row * 132 + c + 3] = q4.w * SCALE;
        kt[(c + 0) * 66 + row] = k4.x;
        kt[(c + 1) * 66 + row] = k4.y;
        kt[(c + 2) * 66 + row] = k4.z;
        kt[(c + 3) * 66 + row] = k4.w;
        vs[row * 132 + c + 0] = v4.x;
        vs[row * 132 + c + 1] = v4.y;
        vs[row * 132 + c + 2] = v4.z;
        vs[row * 132 + c + 3] = v4.w;
    }
    if (tid < 225) bt[tid] = bias_table[tid];
    __syncthreads();

    const int r = tid >> 2;
    const int g = tid & 3;
    const int ry = r >> 3, rx = r & 7;

    unsigned long long acc[8];
#pragma unroll
    for (int j = 0; j < 8; j++) acc[j] = 0ull;
#pragma unroll 4
    for (int d = 0; d < 128; d++) {
        unsigned long long qsp = splat2(qs[r * 132 + d]);
#pragma unroll
        for (int j = 0; j < 8; j++)
            fma2(acc[j], qsp, *(const unsigned long long*)(&kt[d * 66 + 2 * g + 8 * j]));
    }

    float e[16];
    float mx = -1e30f;
#pragma unroll
    for (int j = 0; j < 8; j++) {
        float lo, hi; unpack2(acc[j], lo, hi);
        int bidx = (ry - j + 7) * 15 + (rx - 2 * g + 7);
        lo += bt[bidx];
        hi += bt[bidx - 1];
        e[2 * j]     = lo;
        e[2 * j + 1] = hi;
        mx = fmaxf(mx, fmaxf(lo, hi));
    }
    mx = fmaxf(mx, __shfl_xor_sync(0xffffffffu, mx, 1));
    mx = fmaxf(mx, __shfl_xor_sync(0xffffffffu, mx, 2));
    float s = 0.0f;
#pragma unroll
    for (int i = 0; i < 16; i++) { e[i] = __expf(e[i] - mx); s += e[i]; }
    s += __shfl_xor_sync(0xffffffffu, s, 1);
    s += __shfl_xor_sync(0xffffffffu, s, 2);
    float inv = 1.0f / s;
#pragma unroll
    for (int j = 0; j < 8; j++) {
        at[r * 65 + 2 * g + 8 * j]     = e[2 * j]     * inv;
        at[r * 65 + 2 * g + 8 * j + 1] = e[2 * j + 1] * inv;
    }
    __syncwarp();

    unsigned long long o2[16];
#pragma unroll
    for (int j = 0; j < 16; j++) o2[j] = 0ull;
    for (int m = 0; m < 64; m++) {
        unsigned long long a2 = splat2(at[r * 65 + m]);
#pragma unroll
        for (int jc = 0; jc < 8; jc++) {
            ulonglong2 vv = *(const ulonglong2*)(&vs[m * 132 + g * 4 + 16 * jc]);
            fma2(o2[2 * jc],     a2, vv.x);
            fma2(o2[2 * jc + 1], a2, vv.y);
        }
    }
    __nv_bfloat16* op = out + ((long)(wi * 64 + r)) * DIMC + head * 128;
#pragma unroll
    for (int jc = 0; jc < 8; jc++) {
        float4 f;
        unpack2(o2[2 * jc],     f.x, f.y);
        unpack2(o2[2 * jc + 1], f.z, f.w);
        uint2 pk;
        pk.x = pack_bf2(f.x, f.y);
        pk.y = pack_bf2(f.z, f.w);
        *(uint2*)(op + g * 4 + 16 * jc) = pk;
    }
}

// ---------------------------------------------------------------------------
extern "C" void kernel_launch(void* const* d_in, const int* in_sizes, int n_in,
                              void* d_out, int out_size)
{
    const float* x      = (const float*)d_in[0];
    const float* ln1_g  = (const float*)d_in[1];
    const float* ln1_b  = (const float*)d_in[2];
    const float* qkv_w  = (const float*)d_in[3];
    const float* qkv_b  = (const float*)d_in[4];
    const float* proj_w = (const float*)d_in[5];
    const float* proj_b = (const float*)d_in[6];
    const float* btab   = (const float*)d_in[7];
    const float* ln2_g  = (const float*)d_in[8];
    const float* ln2_b  = (const float*)d_in[9];
    const float* mlp_w1 = (const float*)d_in[10];
    const float* mlp_b1 = (const float*)d_in[11];
    const float* mlp_w2 = (const float*)d_in[12];
    const float* mlp_b2 = (const float*)d_in[13];
    float* outp = (float*)d_out;

    float* S = nullptr;
    cudaGetSymbolAddress((void**)&S, g_scratch);
    __nv_bfloat16* hw   = (__nv_bfloat16*)(S + OFF_HW);
    float*         qkv  = S + OFF_QKV;
    __nv_bfloat16* aout = (__nv_bfloat16*)(S + OFF_AOUT);
    float*         x2   = S + OFF_X2;
    __nv_bfloat16* h2n  = (__nv_bfloat16*)(S + OFF_H2N);
    __nv_bfloat16* m1   = (__nv_bfloat16*)(S + OFF_MLP1);
    __nv_bfloat16* wq   = (__nv_bfloat16*)(S + OFF_WQKV);
    __nv_bfloat16* wp   = (__nv_bfloat16*)(S + OFF_WPROJ);
    __nv_bfloat16* w1   = (__nv_bfloat16*)(S + OFF_WM1);
    __nv_bfloat16* w2   = (__nv_bfloat16*)(S + OFF_WM2);

    cudaFuncSetAttribute(attn_kernel, cudaFuncAttributeMaxDynamicSharedMemorySize,
                         ATTN_SMEM_BYTES);
    cudaFuncSetAttribute(mma_gemm, cudaFuncAttributeMaxDynamicSharedMemorySize,
                         GSMEM_BYTES);

    // transposed bf16 weights [N][K]
    transpose_kernel<<<dim3(48, 16), dim3(32, 8)>>>(qkv_w, wq, 512, 1536);
    transpose_kernel<<<dim3(16, 16), dim3(32, 8)>>>(proj_w, wp, 512, 512);
    transpose_kernel<<<dim3(64, 16), dim3(32, 8)>>>(mlp_w1, w1, 512, 2048);
    transpose_kernel<<<dim3(16, 64), dim3(32, 8)>>>(mlp_w2, w2, 2048, 512);

    // 1) LN1 + cyclic shift + window partition (bf16 out)
    ln_kernel<<<TOKENS, 128>>>(x, ln1_g, ln1_b, hw, 1);
    // 2) QKV GEMM (f32 out)
    mma_gemm<<<dim3(12, 256), 256, GSMEM_BYTES>>>(hw, wq, qkv_b, qkv,
                                                  512, 1536, 0, nullptr);
    // 3) windowed attention (bf16 out)
    attn_kernel<<<NWIN * 4, 256, ATTN_SMEM_BYTES>>>(qkv, btab, aout);
    // 4) proj + window reverse + unshift + residual(x) -> x2 (f32)
    mma_gemm<<<dim3(4, 256), 256, GSMEM_BYTES>>>(aout, wp, proj_b, x2,
                                                 512, 512, 1, x);
    // 5) LN2 (bf16 out)
    ln_kernel<<<TOKENS, 128>>>(x2, ln2_g, ln2_b, h2n, 0);
    // 6) MLP1 + exact GELU (bf16 out)
    mma_gemm<<<dim3(16, 256), 256, GSMEM_BYTES>>>(h2n, w1, mlp_b1, m1,
                                                  512, 2048, 2, nullptr);
    // 7) MLP2 + residual(x2) -> output (f32)
    mma_gemm<<<dim3(4, 256), 256, GSMEM_BYTES>>>(m1, w2, mlp_b2, outp,
                                                 2048, 512, 3, x2);
}

// round 13
// speedup vs baseline: 1.6739x; 1.6739x over previous
#include <cuda_runtime.h>
#include <cuda_bf16.h>
#include <cstdint>

// ---------------------------------------------------------------------------
// Swin Transformer block, bf16 mma.sync m16n8k16 GEMMs (ldmatrix fragments),
// 256x128 CTA tile, 512 threads (16 warps, 4m x 4n), cp.async 4-stage.
// B=16, H=W=64, C=512, NH=4, WS=8, SS=4
// ---------------------------------------------------------------------------

#define TOKENS   65536
#define DIMC     512
#define NWIN     1024

// scratch layout (float-indexed offsets; bf16 regions reinterpret, use <= half)
#define OFF_HW     0L
#define OFF_QKV    33554432L
#define OFF_AOUT   134217728L
#define OFF_X2     167772160L
#define OFF_H2N    201326592L
#define OFF_MLP1   234881024L
#define OFF_WQKV   369098752L      // transposed bf16 weights [N][K]
#define OFF_WPROJ  369885184L
#define OFF_WM1    370147328L
#define OFF_WM2    371195904L
#define SCRATCH_FLOATS 372244480L

__device__ float g_scratch[SCRATCH_FLOATS];

// ---------------- helpers ----------------
__device__ __forceinline__ uint32_t smem_u32(const void* p) {
    uint32_t a;
    asm("{ .reg .u64 t; cvta.to.shared.u64 t, %1; cvt.u32.u64 %0, t; }" : "=r"(a) : "l"(p));
    return a;
}
__device__ __forceinline__ void cp_async16(uint32_t dst, const void* src) {
    asm volatile("cp.async.cg.shared.global [%0], [%1], 16;" :: "r"(dst), "l"(src));
}
__device__ __forceinline__ void ldsm_x4(uint32_t& r0, uint32_t& r1, uint32_t& r2,
                                        uint32_t& r3, uint32_t addr) {
    asm volatile("ldmatrix.sync.aligned.m8n8.x4.shared.b16 {%0,%1,%2,%3}, [%4];"
                 : "=r"(r0), "=r"(r1), "=r"(r2), "=r"(r3) : "r"(addr));
}
__device__ __forceinline__ void mma_bf16(float* d, const uint32_t* a, const uint32_t* b) {
    asm volatile(
        "mma.sync.aligned.m16n8k16.row.col.f32.bf16.bf16.f32 "
        "{%0,%1,%2,%3}, {%4,%5,%6,%7}, {%8,%9}, {%0,%1,%2,%3};"
        : "+f"(d[0]), "+f"(d[1]), "+f"(d[2]), "+f"(d[3])
        : "r"(a[0]), "r"(a[1]), "r"(a[2]), "r"(a[3]), "r"(b[0]), "r"(b[1]));
}
__device__ __forceinline__ uint32_t pack_bf2(float x, float y) {
    __nv_bfloat162 p = __float22bfloat162_rn(make_float2(x, y));
    return *(uint32_t*)&p;
}

// ---------------------------------------------------------------------------
// Weight transpose [K,N] -> [N,K], bf16
// ---------------------------------------------------------------------------
__global__ __launch_bounds__(256) void transpose_kernel(
    const float* __restrict__ W, __nv_bfloat16* __restrict__ Wt, int K, int N)
{
    __shared__ float t[32][33];
    int n0 = blockIdx.x * 32, k0 = blockIdx.y * 32;
#pragma unroll
    for (int i = threadIdx.y; i < 32; i += 8)
        t[i][threadIdx.x] = W[(long)(k0 + i) * N + n0 + threadIdx.x];
    __syncthreads();
#pragma unroll
    for (int i = threadIdx.y; i < 32; i += 8)
        Wt[(long)(n0 + i) * K + k0 + threadIdx.x] = __float2bfloat16_rn(t[threadIdx.x][i]);
}

// ---------------------------------------------------------------------------
// LayerNorm (+ optional shift & window partition of SOURCE row), bf16 output
// ---------------------------------------------------------------------------
__global__ __launch_bounds__(128) void ln_kernel(
    const float* __restrict__ src, const float* __restrict__ gamma,
    const float* __restrict__ beta, __nv_bfloat16* __restrict__ dst, int do_shift)
{
    int r = blockIdx.x;
    long srow = r;
    if (do_shift) {
        int wi = r >> 6, n = r & 63;
        int b  = wi >> 6, wrem = wi & 63;
        int wy = wrem >> 3, wx = wrem & 7;
        int iy = n >> 3,   ix = n & 7;
        int h = (wy * 8 + iy + 4) & 63;
        int w = (wx * 8 + ix + 4) & 63;
        srow = ((long)b * 64 + h) * 64 + w;
    }
    int c = threadIdx.x * 4;
    float4 v = *(const float4*)(src + srow * DIMC + c);
    float s  = v.x + v.y + v.z + v.w;
    float ss = v.x * v.x + v.y * v.y + v.z * v.z + v.w * v.w;
#pragma unroll
    for (int o = 16; o; o >>= 1) {
        s  += __shfl_xor_sync(0xffffffffu, s,  o);
        ss += __shfl_xor_sync(0xffffffffu, ss, o);
    }
    __shared__ float red[8];
    int warp = threadIdx.x >> 5, lane = threadIdx.x & 31;
    if (lane == 0) { red[warp] = s; red[warp + 4] = ss; }
    __syncthreads();
    s  = red[0] + red[1] + red[2] + red[3];
    ss = red[4] + red[5] + red[6] + red[7];
    float mean = s * (1.0f / 512.0f);
    float var  = ss * (1.0f / 512.0f) - mean * mean;
    float inv  = rsqrtf(var + 1e-5f);
    float4 g4 = *(const float4*)(gamma + c);
    float4 b4 = *(const float4*)(beta + c);
    uint2 pk;
    pk.x = pack_bf2((v.x - mean) * inv * g4.x + b4.x, (v.y - mean) * inv * g4.y + b4.y);
    pk.y = pack_bf2((v.z - mean) * inv * g4.z + b4.z, (v.w - mean) * inv * g4.w + b4.w);
    *(uint2*)(dst + (long)r * DIMC + c) = pk;
}

// ---------------------------------------------------------------------------
// bf16 mma GEMM: C[M,N] = A[M,K] @ Wt[N,K]^T   (A, Wt bf16; acc fp32)
// CTA tile 256x128, BK=32 halves, 4-stage cp.async, 512 threads,
// 16 warps (4m x 4n), warp tile 64x32: per ks 4+2 ldsm.x4 + 16 mma.
// smem stride 40 halves (80B) -> conflict-free ldmatrix rows.
// Loader: ar=tid>>2 (0..127), ac=(tid&3)*8; A 2 iters, B 1 iter.
// Epilogue: regs -> smem staging[256][68] (fp32), two 64-col passes.
// modes: 0 bias(f32 out) | 1 bias+winrev+residual(f32) | 2 bias+GELU(bf16 out)
//        | 3 bias+residual(f32)
// ---------------------------------------------------------------------------
#define LDH 40
#define A_HALVES (256 * LDH)                       // 10240
#define STAGE_HALVES (256 * LDH + 128 * LDH)       // 15360 (30720 B)
#define NSTAGE 4
#define GSMEM_BYTES (NSTAGE * STAGE_HALVES * 2)    // 122880
#define LDS 68

__global__ __launch_bounds__(512, 1) void mma_gemm(
    const __nv_bfloat16* __restrict__ A, const __nv_bfloat16* __restrict__ Wt,
    const float* __restrict__ bias, void* __restrict__ Cv,
    int K, int N, int mode, const float* __restrict__ res)
{
    extern __shared__ __align__(16) float sraw[];
    const uint32_t sb = smem_u32(sraw);

    const int tid  = threadIdx.x;
    const int lane = tid & 31;
    const int warp = tid >> 5;    // 0..15
    const int wm   = warp & 3;    // 0..3 -> 64-row slab
    const int wn   = warp >> 2;   // 0..3 -> 32-col slab
    const long brow = (long)blockIdx.y * 256;
    const int  bcol = blockIdx.x * 128;
    const int  Cn = K >> 5;

    // global->smem geometry: 16B (8 halves) per cp; chunk = 32 halves/row
    const int ar = tid >> 2;             // 0..127
    const int ac = (tid & 3) << 3;       // 0,8,16,24 halves

    auto issue_load = [&](int c, int s) {
        const int k0 = c * 32;                       // halves
        const uint32_t as = sb + (uint32_t)(s * STAGE_HALVES) * 2;
        const uint32_t bs = as + A_HALVES * 2;
#pragma unroll
        for (int i = 0; i < 2; i++) {
            int r = ar + i * 128;
            cp_async16(as + (r * LDH + ac) * 2, A + (brow + r) * (long)K + k0 + ac);
        }
        cp_async16(bs + (ar * LDH + ac) * 2, Wt + (long)(bcol + ar) * K + k0 + ac);
        asm volatile("cp.async.commit_group;" ::: "memory");
    };

    float acc[4][4][4];
#pragma unroll
    for (int mt = 0; mt < 4; mt++)
#pragma unroll
        for (int nt = 0; nt < 4; nt++)
#pragma unroll
            for (int q = 0; q < 4; q++) acc[mt][nt][q] = 0.0f;

    // ldmatrix per-lane geometry
    const int lrow = (lane & 7) + ((lane >> 3) & 1) * 8;   // 0..15
    const int lcol = (lane >> 4) * 8;                       // halves: 0 or 8

    issue_load(0, 0);
    issue_load(1, 1);
    issue_load(2, 2);

    for (int c = 0; c < Cn; c++) {
        asm volatile("cp.async.wait_group 2;" ::: "memory");
        __syncthreads();
        if (c + NSTAGE - 1 < Cn) issue_load(c + NSTAGE - 1, (c + NSTAGE - 1) % NSTAGE);
        else asm volatile("cp.async.commit_group;" ::: "memory");

        const uint32_t stage = sb + (uint32_t)((c % NSTAGE) * STAGE_HALVES) * 2;
        const uint32_t a_off = stage + ((wm * 64 + lrow) * LDH + lcol) * 2;
        const uint32_t b_off = stage + A_HALVES * 2 + ((wn * 32 + lrow) * LDH + lcol) * 2;
#pragma unroll
        for (int ks = 0; ks < 2; ks++) {
            uint32_t af[4][4], bf[4][2];
#pragma unroll
            for (int mt = 0; mt < 4; mt++)
                ldsm_x4(af[mt][0], af[mt][1], af[mt][2], af[mt][3],
                        a_off + (mt * 16 * LDH + ks * 16) * 2);
#pragma unroll
            for (int np = 0; np < 2; np++) {
                uint32_t r0, r1, r2, r3;
                ldsm_x4(r0, r1, r2, r3, b_off + (np * 16 * LDH + ks * 16) * 2);
                bf[2 * np][0] = r0; bf[2 * np][1] = r2;
                bf[2 * np + 1][0] = r1; bf[2 * np + 1][1] = r3;
            }
#pragma unroll
            for (int mt = 0; mt < 4; mt++)
#pragma unroll
                for (int nt = 0; nt < 4; nt++)
                    mma_bf16(acc[mt][nt], af[mt], bf[nt]);
        }
    }
    asm volatile("cp.async.wait_group 0;" ::: "memory");

    // ---------------- epilogue: two 64-column passes via shared staging ----
    const int gr  = lane >> 2;
    const int tg2 = (lane & 3) * 2;
#pragma unroll 1
    for (int pass = 0; pass < 2; pass++) {
        __syncthreads();
        if ((wn >> 1) == pass) {
            const int scol = (wn & 1) * 32;
#pragma unroll
            for (int mt = 0; mt < 4; mt++)
#pragma unroll
                for (int nt = 0; nt < 4; nt++) {
                    float* st = sraw + (wm * 64 + mt * 16 + gr) * LDS + scol + nt * 8 + tg2;
                    *(float2*)st = make_float2(acc[mt][nt][0], acc[mt][nt][1]);
                    *(float2*)(st + 8 * LDS) = make_float2(acc[mt][nt][2], acc[mt][nt][3]);
                }
        }
        __syncthreads();

        const int r  = tid >> 1;          // 0..255
        const int ch = (tid & 1) * 32;
        long rr = brow + r;
        long orow = rr;
        if (mode == 1) {
            int ri = (int)rr;
            int wi = ri >> 6, n = ri & 63;
            int b  = wi >> 6, wrem = wi & 63;
            int wy = wrem >> 3, wx = wrem & 7;
            int iy = n >> 3,   ix = n & 7;
            int h = (wy * 8 + iy + 4) & 63;
            int w = (wx * 8 + ix + 4) & 63;
            orow = ((long)b * 64 + h) * 64 + w;
        }
        float* crow = (mode == 2) ? nullptr : (float*)Cv + orow * (long)N;
        __nv_bfloat16* crow_bf = (mode == 2)
            ? (__nv_bfloat16*)Cv + orow * (long)N : nullptr;
        const float* rrow = (mode == 1 || mode == 3) ? res + orow * (long)N : nullptr;
#pragma unroll
        for (int j = 0; j < 32; j += 4) {
            int col = bcol + pass * 64 + ch + j;
            float4 v = *(const float4*)(sraw + r * LDS + ch + j);
            float4 b4 = *(const float4*)(bias + col);
            v.x += b4.x; v.y += b4.y; v.z += b4.z; v.w += b4.w;
            if (mode == 2) {
                v.x = 0.5f * v.x * (1.0f + erff(v.x * 0.70710678118654752f));
                v.y = 0.5f * v.y * (1.0f + erff(v.y * 0.70710678118654752f));
                v.z = 0.5f * v.z * (1.0f + erff(v.z * 0.70710678118654752f));
                v.w = 0.5f * v.w * (1.0f + erff(v.w * 0.70710678118654752f));
                uint2 pk;
                pk.x = pack_bf2(v.x, v.y);
                pk.y = pack_bf2(v.z, v.w);
                *(uint2*)(crow_bf + col) = pk;
            } else {
                if (rrow) {
                    float4 r4 = *(const float4*)(rrow + col);
                    v.x += r4.x; v.y += r4.y; v.z += r4.z; v.w += r4.w;
                }
                *(float4*)(crow + col) = v;
            }
        }
    }
}

// ---------------------------------------------------------------------------
// Windowed attention (SIMT fp32 / f32x2), bf16 output
// ---------------------------------------------------------------------------
__device__ __forceinline__ unsigned long long splat2(float x) {
    unsigned long long r; unsigned u = __float_as_uint(x);
    asm("mov.b64 %0, {%1, %1};" : "=l"(r) : "r"(u));
    return r;
}
__device__ __forceinline__ void unpack2(unsigned long long v, float& lo, float& hi) {
    unsigned a, b;
    asm("mov.b64 {%0, %1}, %2;" : "=r"(a), "=r"(b) : "l"(v));
    lo = __uint_as_float(a); hi = __uint_as_float(b);
}
__device__ __forceinline__ void fma2(unsigned long long& d, unsigned long long a,
                                     unsigned long long b) {
    asm("fma.rn.f32x2 %0, %1, %2, %0;" : "+l"(d) : "l"(a), "l"(b));
}

#define ATTN_SMEM_FLOATS (64*132 + 128*66 + 64*132 + 64*65 + 240)
#define ATTN_SMEM_BYTES  (ATTN_SMEM_FLOATS * 4)

__global__ __launch_bounds__(256, 1) void attn_kernel(
    const float* __restrict__ qkv, const float* __restrict__ bias_table,
    __nv_bfloat16* __restrict__ out)
{
    extern __shared__ float sm[];
    float* qs = sm;
    float* kt = qs + 64 * 132;
    float* vs = kt + 128 * 66;
    float* at = vs + 64 * 132;
    float* bt = at + 64 * 65;

    const int wi   = blockIdx.x >> 2;
    const int head = blockIdx.x & 3;
    const int tid  = threadIdx.x;
    const float SCALE = 0.08838834764831845f;

    const float* base = qkv + (long)wi * 64 * 1536 + head * 128;
    for (int idx = tid; idx < 64 * 32; idx += 256) {
        int row = idx >> 5;
        int c   = (idx & 31) << 2;
        const float* p = base + (long)row * 1536 + c;
        float4 q4 = *(const float4*)(p);
        float4 k4 = *(const float4*)(p + 512);
        float4 v4 = *(const float4*)(p + 1024);
        qs[row * 132 + c + 0] = q4.x * SCALE;
        qs[row * 132 + c + 1] = q4.y * SCALE;
        qs[row * 132 + c + 2] = q4.z * SCALE;
        qs[row * 132 + c + 3] = q4.w * SCALE;
        kt[(c + 0) * 66 + row] = k4.x;
        kt[(c + 1) * 66 + row] = k4.y;
        kt[(c + 2) * 66 + row] = k4.z;
        kt[(c + 3) * 66 + row] = k4.w;
        vs[row * 132 + c + 0] = v4.x;
        vs[row * 132 + c + 1] = v4.y;
        vs[row * 132 + c + 2] = v4.z;
        vs[row * 132 + c + 3] = v4.w;
    }
    if (tid < 225) bt[tid] = bias_table[tid];
    __syncthreads();

    const int r = tid >> 2;
    const int g = tid & 3;
    const int ry = r >> 3, rx = r & 7;

    unsigned long long acc[8];
#pragma unroll
    for (int j = 0; j < 8; j++) acc[j] = 0ull;
#pragma unroll 4
    for (int d = 0; d < 128; d++) {
        unsigned long long qsp = splat2(qs[r * 132 + d]);
#pragma unroll
        for (int j = 0; j < 8; j++)
            fma2(acc[j], qsp, *(const unsigned long long*)(&kt[d * 66 + 2 * g + 8 * j]));
    }

    float e[16];
    float mx = -1e30f;
#pragma unroll
    for (int j = 0; j < 8; j++) {
        float lo, hi; unpack2(acc[j], lo, hi);
        int bidx = (ry - j + 7) * 15 + (rx - 2 * g + 7);
        lo += bt[bidx];
        hi += bt[bidx - 1];
        e[2 * j]     = lo;
        e[2 * j + 1] = hi;
        mx = fmaxf(mx, fmaxf(lo, hi));
    }
    mx = fmaxf(mx, __shfl_xor_sync(0xffffffffu, mx, 1));
    mx = fmaxf(mx, __shfl_xor_sync(0xffffffffu, mx, 2));
    float s = 0.0f;
#pragma unroll
    for (int i = 0; i < 16; i++) { e[i] = __expf(e[i] - mx); s += e[i]; }
    s += __shfl_xor_sync(0xffffffffu, s, 1);
    s += __shfl_xor_sync(0xffffffffu, s, 2);
    float inv = 1.0f / s;
#pragma unroll
    for (int j = 0; j < 8; j++) {
        at[r * 65 + 2 * g + 8 * j]     = e[2 * j]     * inv;
        at[r * 65 + 2 * g + 8 * j + 1] = e[2 * j + 1] * inv;
    }
    __syncwarp();

    unsigned long long o2[16];
#pragma unroll
    for (int j = 0; j < 16; j++) o2[j] = 0ull;
    for (int m = 0; m < 64; m++) {
        unsigned long long a2 = splat2(at[r * 65 + m]);
#pragma unroll
        for (int jc = 0; jc < 8; jc++) {
            ulonglong2 vv = *(const ulonglong2*)(&vs[m * 132 + g * 4 + 16 * jc]);
            fma2(o2[2 * jc],     a2, vv.x);
            fma2(o2[2 * jc + 1], a2, vv.y);
        }
    }
    __nv_bfloat16* op = out + ((long)(wi * 64 + r)) * DIMC + head * 128;
#pragma unroll
    for (int jc = 0; jc < 8; jc++) {
        float4 f;
        unpack2(o2[2 * jc],     f.x, f.y);
        unpack2(o2[2 * jc + 1], f.z, f.w);
        uint2 pk;
        pk.x = pack_bf2(f.x, f.y);
        pk.y = pack_bf2(f.z, f.w);
        *(uint2*)(op + g * 4 + 16 * jc) = pk;
    }
}

// ---------------------------------------------------------------------------
extern "C" void kernel_launch(void* const* d_in, const int* in_sizes, int n_in,
                              void* d_out, int out_size)
{
    const float* x      = (const float*)d_in[0];
    const float* ln1_g  = (const float*)d_in[1];
    const float* ln1_b  = (const float*)d_in[2];
    const float* qkv_w  = (const float*)d_in[3];
    const float* qkv_b  = (const float*)d_in[4];
    const float* proj_w = (const float*)d_in[5];
    const float* proj_b = (const float*)d_in[6];
    const float* btab   = (const float*)d_in[7];
    const float* ln2_g  = (const float*)d_in[8];
    const float* ln2_b  = (const float*)d_in[9];
    const float* mlp_w1 = (const float*)d_in[10];
    const float* mlp_b1 = (const float*)d_in[11];
    const float* mlp_w2 = (const float*)d_in[12];
    const float* mlp_b2 = (const float*)d_in[13];
    float* outp = (float*)d_out;

    float* S = nullptr;
    cudaGetSymbolAddress((void**)&S, g_scratch);
    __nv_bfloat16* hw   = (__nv_bfloat16*)(S + OFF_HW);
    float*         qkv  = S + OFF_QKV;
    __nv_bfloat16* aout = (__nv_bfloat16*)(S + OFF_AOUT);
    float*         x2   = S + OFF_X2;
    __nv_bfloat16* h2n  = (__nv_bfloat16*)(S + OFF_H2N);
    __nv_bfloat16* m1   = (__nv_bfloat16*)(S + OFF_MLP1);
    __nv_bfloat16* wq   = (__nv_bfloat16*)(S + OFF_WQKV);
    __nv_bfloat16* wp   = (__nv_bfloat16*)(S + OFF_WPROJ);
    __nv_bfloat16* w1   = (__nv_bfloat16*)(S + OFF_WM1);
    __nv_bfloat16* w2   = (__nv_bfloat16*)(S + OFF_WM2);

    cudaFuncSetAttribute(attn_kernel, cudaFuncAttributeMaxDynamicSharedMemorySize,
                         ATTN_SMEM_BYTES);
    cudaFuncSetAttribute(mma_gemm, cudaFuncAttributeMaxDynamicSharedMemorySize,
                         GSMEM_BYTES);

    // transposed bf16 weights [N][K]
    transpose_kernel<<<dim3(48, 16), dim3(32, 8)>>>(qkv_w, wq, 512, 1536);
    transpose_kernel<<<dim3(16, 16), dim3(32, 8)>>>(proj_w, wp, 512, 512);
    transpose_kernel<<<dim3(64, 16), dim3(32, 8)>>>(mlp_w1, w1, 512, 2048);
    transpose_kernel<<<dim3(16, 64), dim3(32, 8)>>>(mlp_w2, w2, 2048, 512);

    // 1) LN1 + cyclic shift + window partition (bf16 out)
    ln_kernel<<<TOKENS, 128>>>(x, ln1_g, ln1_b, hw, 1);
    // 2) QKV GEMM (f32 out)
    mma_gemm<<<dim3(12, 256), 512, GSMEM_BYTES>>>(hw, wq, qkv_b, qkv,
                                                  512, 1536, 0, nullptr);
    // 3) windowed attention (bf16 out)
    attn_kernel<<<NWIN * 4, 256, ATTN_SMEM_BYTES>>>(qkv, btab, aout);
    // 4) proj + window reverse + unshift + residual(x) -> x2 (f32)
    mma_gemm<<<dim3(4, 256), 512, GSMEM_BYTES>>>(aout, wp, proj_b, x2,
                                                 512, 512, 1, x);
    // 5) LN2 (bf16 out)
    ln_kernel<<<TOKENS, 128>>>(x2, ln2_g, ln2_b, h2n, 0);
    // 6) MLP1 + exact GELU (bf16 out)
    mma_gemm<<<dim3(16, 256), 512, GSMEM_BYTES>>>(h2n, w1, mlp_b1, m1,
                                                  512, 2048, 2, nullptr);
    // 7) MLP2 + residual(x2) -> output (f32)
    mma_gemm<<<dim3(4, 256), 512, GSMEM_BYTES>>>(m1, w2, mlp_b2, outp,
                                                 2048, 512, 3, x2);
}

// round 14
// speedup vs baseline: 1.7837x; 1.0656x over previous
#include <cuda_runtime.h>
#include <cuda_bf16.h>
#include <cstdint>

// ---------------------------------------------------------------------------
// Swin Transformer block, bf16 mma.sync m16n8k16 GEMMs (ldmatrix fragments),
// 128x128 CTA tile, 256 threads (8 warps, 4m x 2n), cp.async 4-stage,
// 2 CTAs/SM. B=16, H=W=64, C=512, NH=4, WS=8, SS=4
// ---------------------------------------------------------------------------

#define TOKENS   65536
#define DIMC     512
#define NWIN     1024

// scratch layout (float-indexed offsets; bf16 regions reinterpret, use <= half)
#define OFF_HW     0L
#define OFF_QKV    33554432L
#define OFF_AOUT   134217728L
#define OFF_X2     167772160L
#define OFF_H2N    201326592L
#define OFF_MLP1   234881024L
#define OFF_WQKV   369098752L      // transposed bf16 weights [N][K]
#define OFF_WPROJ  369885184L
#define OFF_WM1    370147328L
#define OFF_WM2    371195904L
#define SCRATCH_FLOATS 372244480L

__device__ float g_scratch[SCRATCH_FLOATS];

// ---------------- helpers ----------------
__device__ __forceinline__ uint32_t smem_u32(const void* p) {
    uint32_t a;
    asm("{ .reg .u64 t; cvta.to.shared.u64 t, %1; cvt.u32.u64 %0, t; }" : "=r"(a) : "l"(p));
    return a;
}
__device__ __forceinline__ void cp_async16(uint32_t dst, const void* src) {
    asm volatile("cp.async.cg.shared.global [%0], [%1], 16;" :: "r"(dst), "l"(src));
}
__device__ __forceinline__ void ldsm_x4(uint32_t& r0, uint32_t& r1, uint32_t& r2,
                                        uint32_t& r3, uint32_t addr) {
    asm volatile("ldmatrix.sync.aligned.m8n8.x4.shared.b16 {%0,%1,%2,%3}, [%4];"
                 : "=r"(r0), "=r"(r1), "=r"(r2), "=r"(r3) : "r"(addr));
}
__device__ __forceinline__ void mma_bf16(float* d, const uint32_t* a, const uint32_t* b) {
    asm volatile(
        "mma.sync.aligned.m16n8k16.row.col.f32.bf16.bf16.f32 "
        "{%0,%1,%2,%3}, {%4,%5,%6,%7}, {%8,%9}, {%0,%1,%2,%3};"
        : "+f"(d[0]), "+f"(d[1]), "+f"(d[2]), "+f"(d[3])
        : "r"(a[0]), "r"(a[1]), "r"(a[2]), "r"(a[3]), "r"(b[0]), "r"(b[1]));
}
__device__ __forceinline__ uint32_t pack_bf2(float x, float y) {
    __nv_bfloat162 p = __float22bfloat162_rn(make_float2(x, y));
    return *(uint32_t*)&p;
}

// ---------------------------------------------------------------------------
// Weight transpose [K,N] -> [N,K], bf16
// ---------------------------------------------------------------------------
__global__ __launch_bounds__(256) void transpose_kernel(
    const float* __restrict__ W, __nv_bfloat16* __restrict__ Wt, int K, int N)
{
    __shared__ float t[32][33];
    int n0 = blockIdx.x * 32, k0 = blockIdx.y * 32;
#pragma unroll
    for (int i = threadIdx.y; i < 32; i += 8)
        t[i][threadIdx.x] = W[(long)(k0 + i) * N + n0 + threadIdx.x];
    __syncthreads();
#pragma unroll
    for (int i = threadIdx.y; i < 32; i += 8)
        Wt[(long)(n0 + i) * K + k0 + threadIdx.x] = __float2bfloat16_rn(t[threadIdx.x][i]);
}

// ---------------------------------------------------------------------------
// LayerNorm (+ optional shift & window partition of SOURCE row), bf16 output
// ---------------------------------------------------------------------------
__global__ __launch_bounds__(128) void ln_kernel(
    const float* __restrict__ src, const float* __restrict__ gamma,
    const float* __restrict__ beta, __nv_bfloat16* __restrict__ dst, int do_shift)
{
    int r = blockIdx.x;
    long srow = r;
    if (do_shift) {
        int wi = r >> 6, n = r & 63;
        int b  = wi >> 6, wrem = wi & 63;
        int wy = wrem >> 3, wx = wrem & 7;
        int iy = n >> 3,   ix = n & 7;
        int h = (wy * 8 + iy + 4) & 63;
        int w = (wx * 8 + ix + 4) & 63;
        srow = ((long)b * 64 + h) * 64 + w;
    }
    int c = threadIdx.x * 4;
    float4 v = *(const float4*)(src + srow * DIMC + c);
    float s  = v.x + v.y + v.z + v.w;
    float ss = v.x * v.x + v.y * v.y + v.z * v.z + v.w * v.w;
#pragma unroll
    for (int o = 16; o; o >>= 1) {
        s  += __shfl_xor_sync(0xffffffffu, s,  o);
        ss += __shfl_xor_sync(0xffffffffu, ss, o);
    }
    __shared__ float red[8];
    int warp = threadIdx.x >> 5, lane = threadIdx.x & 31;
    if (lane == 0) { red[warp] = s; red[warp + 4] = ss; }
    __syncthreads();
    s  = red[0] + red[1] + red[2] + red[3];
    ss = red[4] + red[5] + red[6] + red[7];
    float mean = s * (1.0f / 512.0f);
    float var  = ss * (1.0f / 512.0f) - mean * mean;
    float inv  = rsqrtf(var + 1e-5f);
    float4 g4 = *(const float4*)(gamma + c);
    float4 b4 = *(const float4*)(beta + c);
    uint2 pk;
    pk.x = pack_bf2((v.x - mean) * inv * g4.x + b4.x, (v.y - mean) * inv * g4.y + b4.y);
    pk.y = pack_bf2((v.z - mean) * inv * g4.z + b4.z, (v.w - mean) * inv * g4.w + b4.w);
    *(uint2*)(dst + (long)r * DIMC + c) = pk;
}

// ---------------------------------------------------------------------------
// bf16 mma GEMM: C[M,N] = A[M,K] @ Wt[N,K]^T   (A, Wt bf16; acc fp32)
// CTA tile 128x128, BK=32 halves, 4-stage cp.async, 2 CTAs/SM,
// 8 warps (4m x 2n), warp tile 32x64: per ks 2+4 ldsm.x4 + 16 mma.
// smem stride 40 halves (80B) -> conflict-free ldmatrix rows.
// Loader: ar=tid>>2 (0..63), ac=(tid&3)*8; A and B 2 iters each.
// Epilogue: regs -> smem staging[128][68] (fp32), two 64-col passes.
// modes: 0 bias(f32 out) | 1 bias+winrev+residual(f32) | 2 bias+GELU(bf16 out)
//        | 3 bias+residual(f32)
// ---------------------------------------------------------------------------
#define LDH 40
#define A_HALVES (128 * LDH)                       // 5120
#define STAGE_HALVES (128 * LDH + 128 * LDH)       // 10240 (20480 B)
#define NSTAGE 4
#define GSMEM_BYTES (NSTAGE * STAGE_HALVES * 2)    // 81920
#define LDS 68

__global__ __launch_bounds__(256, 2) void mma_gemm(
    const __nv_bfloat16* __restrict__ A, const __nv_bfloat16* __restrict__ Wt,
    const float* __restrict__ bias, void* __restrict__ Cv,
    int K, int N, int mode, const float* __restrict__ res)
{
    extern __shared__ __align__(16) float sraw[];
    const uint32_t sb = smem_u32(sraw);

    const int tid  = threadIdx.x;
    const int lane = tid & 31;
    const int warp = tid >> 5;    // 0..7
    const int wm   = warp & 3;    // 0..3 -> 32-row slab
    const int wn   = warp >> 2;   // 0..1 -> 64-col slab
    const long brow = (long)blockIdx.y * 128;
    const int  bcol = blockIdx.x * 128;
    const int  Cn = K >> 5;

    // global->smem geometry: 16B (8 halves) per cp; chunk = 32 halves/row
    const int ar = tid >> 2;             // 0..63
    const int ac = (tid & 3) << 3;       // 0,8,16,24 halves

    auto issue_load = [&](int c, int s) {
        const int k0 = c * 32;                       // halves
        const uint32_t as = sb + (uint32_t)(s * STAGE_HALVES) * 2;
        const uint32_t bs = as + A_HALVES * 2;
#pragma unroll
        for (int i = 0; i < 2; i++) {
            int r = ar + i * 64;
            cp_async16(as + (r * LDH + ac) * 2, A + (brow + r) * (long)K + k0 + ac);
        }
#pragma unroll
        for (int i = 0; i < 2; i++) {
            int r = ar + i * 64;
            cp_async16(bs + (r * LDH + ac) * 2, Wt + (long)(bcol + r) * K + k0 + ac);
        }
        asm volatile("cp.async.commit_group;" ::: "memory");
    };

    float acc[2][8][4];
#pragma unroll
    for (int mt = 0; mt < 2; mt++)
#pragma unroll
        for (int nt = 0; nt < 8; nt++)
#pragma unroll
            for (int q = 0; q < 4; q++) acc[mt][nt][q] = 0.0f;

    // ldmatrix per-lane geometry
    const int lrow = (lane & 7) + ((lane >> 3) & 1) * 8;   // 0..15
    const int lcol = (lane >> 4) * 8;                       // halves: 0 or 8

    issue_load(0, 0);
    issue_load(1, 1);
    issue_load(2, 2);

    for (int c = 0; c < Cn; c++) {
        asm volatile("cp.async.wait_group 2;" ::: "memory");
        __syncthreads();
        if (c + NSTAGE - 1 < Cn) issue_load(c + NSTAGE - 1, (c + NSTAGE - 1) % NSTAGE);
        else asm volatile("cp.async.commit_group;" ::: "memory");

        const uint32_t stage = sb + (uint32_t)((c % NSTAGE) * STAGE_HALVES) * 2;
        const uint32_t a_off = stage + ((wm * 32 + lrow) * LDH + lcol) * 2;
        const uint32_t b_off = stage + A_HALVES * 2 + ((wn * 64 + lrow) * LDH + lcol) * 2;
#pragma unroll
        for (int ks = 0; ks < 2; ks++) {
            uint32_t af[2][4], bf[8][2];
#pragma unroll
            for (int mt = 0; mt < 2; mt++)
                ldsm_x4(af[mt][0], af[mt][1], af[mt][2], af[mt][3],
                        a_off + (mt * 16 * LDH + ks * 16) * 2);
#pragma unroll
            for (int np = 0; np < 4; np++) {
                uint32_t r0, r1, r2, r3;
                ldsm_x4(r0, r1, r2, r3, b_off + (np * 16 * LDH + ks * 16) * 2);
                bf[2 * np][0] = r0; bf[2 * np][1] = r2;
                bf[2 * np + 1][0] = r1; bf[2 * np + 1][1] = r3;
            }
#pragma unroll
            for (int mt = 0; mt < 2; mt++)
#pragma unroll
                for (int nt = 0; nt < 8; nt++)
                    mma_bf16(acc[mt][nt], af[mt], bf[nt]);
        }
    }
    asm volatile("cp.async.wait_group 0;" ::: "memory");

    // ---------------- epilogue: two 64-column passes via shared staging ----
    const int gr  = lane >> 2;
    const int tg2 = (lane & 3) * 2;
#pragma unroll 1
    for (int pass = 0; pass < 2; pass++) {
        __syncthreads();
        if (wn == pass) {
#pragma unroll
            for (int mt = 0; mt < 2; mt++)
#pragma unroll
                for (int nt = 0; nt < 8; nt++) {
                    float* st = sraw + (wm * 32 + mt * 16 + gr) * LDS + nt * 8 + tg2;
                    *(float2*)st = make_float2(acc[mt][nt][0], acc[mt][nt][1]);
                    *(float2*)(st + 8 * LDS) = make_float2(acc[mt][nt][2], acc[mt][nt][3]);
                }
        }
        __syncthreads();

        const int r  = tid >> 1;          // 0..127
        const int ch = (tid & 1) * 32;
        long rr = brow + r;
        long orow = rr;
        if (mode == 1) {
            int ri = (int)rr;
            int wi = ri >> 6, n = ri & 63;
            int b  = wi >> 6, wrem = wi & 63;
            int wy = wrem >> 3, wx = wrem & 7;
            int iy = n >> 3,   ix = n & 7;
            int h = (wy * 8 + iy + 4) & 63;
            int w = (wx * 8 + ix + 4) & 63;
            orow = ((long)b * 64 + h) * 64 + w;
        }
        float* crow = (mode == 2) ? nullptr : (float*)Cv + orow * (long)N;
        __nv_bfloat16* crow_bf = (mode == 2)
            ? (__nv_bfloat16*)Cv + orow * (long)N : nullptr;
        const float* rrow = (mode == 1 || mode == 3) ? res + orow * (long)N : nullptr;
#pragma unroll
        for (int j = 0; j < 32; j += 4) {
            int col = bcol + pass * 64 + ch + j;
            float4 v = *(const float4*)(sraw + r * LDS + ch + j);
            float4 b4 = *(const float4*)(bias + col);
            v.x += b4.x; v.y += b4.y; v.z += b4.z; v.w += b4.w;
            if (mode == 2) {
                v.x = 0.5f * v.x * (1.0f + erff(v.x * 0.70710678118654752f));
                v.y = 0.5f * v.y * (1.0f + erff(v.y * 0.70710678118654752f));
                v.z = 0.5f * v.z * (1.0f + erff(v.z * 0.70710678118654752f));
                v.w = 0.5f * v.w * (1.0f + erff(v.w * 0.70710678118654752f));
                uint2 pk;
                pk.x = pack_bf2(v.x, v.y);
                pk.y = pack_bf2(v.z, v.w);
                *(uint2*)(crow_bf + col) = pk;
            } else {
                if (rrow) {
                    float4 r4 = *(const float4*)(rrow + col);
                    v.x += r4.x; v.y += r4.y; v.z += r4.z; v.w += r4.w;
                }
                *(float4*)(crow + col) = v;
            }
        }
    }
}

// ---------------------------------------------------------------------------
// Windowed attention (SIMT fp32 / f32x2), bf16 output
// ---------------------------------------------------------------------------
__device__ __forceinline__ unsigned long long splat2(float x) {
    unsigned long long r; unsigned u = __float_as_uint(x);
    asm("mov.b64 %0, {%1, %1};" : "=l"(r) : "r"(u));
    return r;
}
__device__ __forceinline__ void unpack2(unsigned long long v, float& lo, float& hi) {
    unsigned a, b;
    asm("mov.b64 {%0, %1}, %2;" : "=r"(a), "=r"(b) : "l"(v));
    lo = __uint_as_float(a); hi = __uint_as_float(b);
}
__device__ __forceinline__ void fma2(unsigned long long& d, unsigned long long a,
                                     unsigned long long b) {
    asm("fma.rn.f32x2 %0, %1, %2, %0;" : "+l"(d) : "l"(a), "l"(b));
}

#define ATTN_SMEM_FLOATS (64*132 + 128*66 + 64*132 + 64*65 + 240)
#define ATTN_SMEM_BYTES  (ATTN_SMEM_FLOATS * 4)

__global__ __launch_bounds__(256, 1) void attn_kernel(
    const float* __restrict__ qkv, const float* __restrict__ bias_table,
    __nv_bfloat16* __restrict__ out)
{
    extern __shared__ float sm[];
    float* qs = sm;
    float* kt = qs + 64 * 132;
    float* vs = kt + 128 * 66;
    float* at = vs + 64 * 132;
    float* bt = at + 64 * 65;

    const int wi   = blockIdx.x >> 2;
    const int head = blockIdx.x & 3;
    const int tid  = threadIdx.x;
    const float SCALE = 0.08838834764831845f;

    const float* base = qkv + (long)wi * 64 * 1536 + head * 128;
    for (int idx = tid; idx < 64 * 32; idx += 256) {
        int row = idx >> 5;
        int c   = (idx & 31) << 2;
        const float* p = base + (long)row * 1536 + c;
        float4 q4 = *(const float4*)(p);
        float4 k4 = *(const float4*)(p + 512);
        float4 v4 = *(const float4*)(p + 1024);
        qs[row * 132 + c + 0] = q4.x * SCALE;
        qs[row * 132 + c + 1] = q4.y * SCALE;
        qs[row * 132 + c + 2] = q4.z * SCALE;
        qs[row * 132 + c + 3] = q4.w * SCALE;
        kt[(c + 0) * 66 + row] = k4.x;
        kt[(c + 1) * 66 + row] = k4.y;
        kt[(c + 2) * 66 + row] = k4.z;
        kt[(c + 3) * 66 + row] = k4.w;
        vs[row * 132 + c + 0] = v4.x;
        vs[row * 132 + c + 1] = v4.y;
        vs[row * 132 + c + 2] = v4.z;
        vs[row * 132 + c + 3] = v4.w;
    }
    if (tid < 225) bt[tid] = bias_table[tid];
    __syncthreads();

    const int r = tid >> 2;
    const int g = tid & 3;
    const int ry = r >> 3, rx = r & 7;

    unsigned long long acc[8];
#pragma unroll
    for (int j = 0; j < 8; j++) acc[j] = 0ull;
#pragma unroll 4
    for (int d = 0; d < 128; d++) {
        unsigned long long qsp = splat2(qs[r * 132 + d]);
#pragma unroll
        for (int j = 0; j < 8; j++)
            fma2(acc[j], qsp, *(const unsigned long long*)(&kt[d * 66 + 2 * g + 8 * j]));
    }

    float e[16];
    float mx = -1e30f;
#pragma unroll
    for (int j = 0; j < 8; j++) {
        float lo, hi; unpack2(acc[j], lo, hi);
        int bidx = (ry - j + 7) * 15 + (rx - 2 * g + 7);
        lo += bt[bidx];
        hi += bt[bidx - 1];
        e[2 * j]     = lo;
        e[2 * j + 1] = hi;
        mx = fmaxf(mx, fmaxf(lo, hi));
    }
    mx = fmaxf(mx, __shfl_xor_sync(0xffffffffu, mx, 1));
    mx = fmaxf(mx, __shfl_xor_sync(0xffffffffu, mx, 2));
    float s = 0.0f;
#pragma unroll
    for (int i = 0; i < 16; i++) { e[i] = __expf(e[i] - mx); s += e[i]; }
    s += __shfl_xor_sync(0xffffffffu, s, 1);
    s += __shfl_xor_sync(0xffffffffu, s, 2);
    float inv = 1.0f / s;
#pragma unroll
    for (int j = 0; j < 8; j++) {
        at[r * 65 + 2 * g + 8 * j]     = e[2 * j]     * inv;
        at[r * 65 + 2 * g + 8 * j + 1] = e[2 * j + 1] * inv;
    }
    __syncwarp();

    unsigned long long o2[16];
#pragma unroll
    for (int j = 0; j < 16; j++) o2[j] = 0ull;
    for (int m = 0; m < 64; m++) {
        unsigned long long a2 = splat2(at[r * 65 + m]);
#pragma unroll
        for (int jc = 0; jc < 8; jc++) {
            ulonglong2 vv = *(const ulonglong2*)(&vs[m * 132 + g * 4 + 16 * jc]);
            fma2(o2[2 * jc],     a2, vv.x);
            fma2(o2[2 * jc + 1], a2, vv.y);
        }
    }
    __nv_bfloat16* op = out + ((long)(wi * 64 + r)) * DIMC + head * 128;
#pragma unroll
    for (int jc = 0; jc < 8; jc++) {
        float4 f;
        unpack2(o2[2 * jc],     f.x, f.y);
        unpack2(o2[2 * jc + 1], f.z, f.w);
        uint2 pk;
        pk.x = pack_bf2(f.x, f.y);
        pk.y = pack_bf2(f.z, f.w);
        *(uint2*)(op + g * 4 + 16 * jc) = pk;
    }
}

// ---------------------------------------------------------------------------
extern "C" void kernel_launch(void* const* d_in, const int* in_sizes, int n_in,
                              void* d_out, int out_size)
{
    const float* x      = (const float*)d_in[0];
    const float* ln1_g  = (const float*)d_in[1];
    const float* ln1_b  = (const float*)d_in[2];
    const float* qkv_w  = (const float*)d_in[3];
    const float* qkv_b  = (const float*)d_in[4];
    const float* proj_w = (const float*)d_in[5];
    const float* proj_b = (const float*)d_in[6];
    const float* btab   = (const float*)d_in[7];
    const float* ln2_g  = (const float*)d_in[8];
    const float* ln2_b  = (const float*)d_in[9];
    const float* mlp_w1 = (const float*)d_in[10];
    const float* mlp_b1 = (const float*)d_in[11];
    const float* mlp_w2 = (const float*)d_in[12];
    const float* mlp_b2 = (const float*)d_in[13];
    float* outp = (float*)d_out;

    float* S = nullptr;
    cudaGetSymbolAddress((void**)&S, g_scratch);
    __nv_bfloat16* hw   = (__nv_bfloat16*)(S + OFF_HW);
    float*         qkv  = S + OFF_QKV;
    __nv_bfloat16* aout = (__nv_bfloat16*)(S + OFF_AOUT);
    float*         x2   = S + OFF_X2;
    __nv_bfloat16* h2n  = (__nv_bfloat16*)(S + OFF_H2N);
    __nv_bfloat16* m1   = (__nv_bfloat16*)(S + OFF_MLP1);
    __nv_bfloat16* wq   = (__nv_bfloat16*)(S + OFF_WQKV);
    __nv_bfloat16* wp   = (__nv_bfloat16*)(S + OFF_WPROJ);
    __nv_bfloat16* w1   = (__nv_bfloat16*)(S + OFF_WM1);
    __nv_bfloat16* w2   = (__nv_bfloat16*)(S + OFF_WM2);

    cudaFuncSetAttribute(attn_kernel, cudaFuncAttributeMaxDynamicSharedMemorySize,
                         ATTN_SMEM_BYTES);
    cudaFuncSetAttribute(mma_gemm, cudaFuncAttributeMaxDynamicSharedMemorySize,
                         GSMEM_BYTES);

    // transposed bf16 weights [N][K]
    transpose_kernel<<<dim3(48, 16), dim3(32, 8)>>>(qkv_w, wq, 512, 1536);
    transpose_kernel<<<dim3(16, 16), dim3(32, 8)>>>(proj_w, wp, 512, 512);
    transpose_kernel<<<dim3(64, 16), dim3(32, 8)>>>(mlp_w1, w1, 512, 2048);
    transpose_kernel<<<dim3(16, 64), dim3(32, 8)>>>(mlp_w2, w2, 2048, 512);

    // 1) LN1 + cyclic shift + window partition (bf16 out)
    ln_kernel<<<TOKENS, 128>>>(x, ln1_g, ln1_b, hw, 1);
    // 2) QKV GEMM (f32 out)
    mma_gemm<<<dim3(12, 512), 256, GSMEM_BYTES>>>(hw, wq, qkv_b, qkv,
                                                  512, 1536, 0, nullptr);
    // 3) windowed attention (bf16 out)
    attn_kernel<<<NWIN * 4, 256, ATTN_SMEM_BYTES>>>(qkv, btab, aout);
    // 4) proj + window reverse + unshift + residual(x) -> x2 (f32)
    mma_gemm<<<dim3(4, 512), 256, GSMEM_BYTES>>>(aout, wp, proj_b, x2,
                                                 512, 512, 1, x);
    // 5) LN2 (bf16 out)
    ln_kernel<<<TOKENS, 128>>>(x2, ln2_g, ln2_b, h2n, 0);
    // 6) MLP1 + exact GELU (bf16 out)
    mma_gemm<<<dim3(16, 512), 256, GSMEM_BYTES>>>(h2n, w1, mlp_b1, m1,
                                                  512, 2048, 2, nullptr);
    // 7) MLP2 + residual(x2) -> output (f32)
    mma_gemm<<<dim3(4, 512), 256, GSMEM_BYTES>>>(m1, w2, mlp_b2, outp,
                                                 2048, 512, 3, x2);
}

// round 15
// speedup vs baseline: 1.9517x; 1.0941x over previous
#include <cuda_runtime.h>
#include <cuda_bf16.h>
#include <cstdint>

// ---------------------------------------------------------------------------
// Swin Transformer block, bf16 mma.sync m16n8k16 GEMMs (ldmatrix fragments),
// 128x128 CTA tile, 2 CTAs/SM; register-blocked SIMT attention; warp-row LN.
// B=16, H=W=64, C=512, NH=4, WS=8, SS=4
// ---------------------------------------------------------------------------

#define TOKENS   65536
#define DIMC     512
#define NWIN     1024

// scratch layout (float-indexed offsets; bf16 regions reinterpret, use <= half)
#define OFF_HW     0L
#define OFF_QKV    33554432L
#define OFF_AOUT   134217728L
#define OFF_X2     167772160L
#define OFF_H2N    201326592L
#define OFF_MLP1   234881024L
#define OFF_WQKV   369098752L      // transposed bf16 weights [N][K]
#define OFF_WPROJ  369885184L
#define OFF_WM1    370147328L
#define OFF_WM2    371195904L
#define SCRATCH_FLOATS 372244480L

__device__ float g_scratch[SCRATCH_FLOATS];

// ---------------- helpers ----------------
__device__ __forceinline__ uint32_t smem_u32(const void* p) {
    uint32_t a;
    asm("{ .reg .u64 t; cvta.to.shared.u64 t, %1; cvt.u32.u64 %0, t; }" : "=r"(a) : "l"(p));
    return a;
}
__device__ __forceinline__ void cp_async16(uint32_t dst, const void* src) {
    asm volatile("cp.async.cg.shared.global [%0], [%1], 16;" :: "r"(dst), "l"(src));
}
__device__ __forceinline__ void ldsm_x4(uint32_t& r0, uint32_t& r1, uint32_t& r2,
                                        uint32_t& r3, uint32_t addr) {
    asm volatile("ldmatrix.sync.aligned.m8n8.x4.shared.b16 {%0,%1,%2,%3}, [%4];"
                 : "=r"(r0), "=r"(r1), "=r"(r2), "=r"(r3) : "r"(addr));
}
__device__ __forceinline__ void mma_bf16(float* d, const uint32_t* a, const uint32_t* b) {
    asm volatile(
        "mma.sync.aligned.m16n8k16.row.col.f32.bf16.bf16.f32 "
        "{%0,%1,%2,%3}, {%4,%5,%6,%7}, {%8,%9}, {%0,%1,%2,%3};"
        : "+f"(d[0]), "+f"(d[1]), "+f"(d[2]), "+f"(d[3])
        : "r"(a[0]), "r"(a[1]), "r"(a[2]), "r"(a[3]), "r"(b[0]), "r"(b[1]));
}
__device__ __forceinline__ uint32_t pack_bf2(float x, float y) {
    __nv_bfloat162 p = __float22bfloat162_rn(make_float2(x, y));
    return *(uint32_t*)&p;
}

// ---------------------------------------------------------------------------
// Weight transpose [K,N] -> [N,K], bf16
// ---------------------------------------------------------------------------
__global__ __launch_bounds__(256) void transpose_kernel(
    const float* __restrict__ W, __nv_bfloat16* __restrict__ Wt, int K, int N)
{
    __shared__ float t[32][33];
    int n0 = blockIdx.x * 32, k0 = blockIdx.y * 32;
#pragma unroll
    for (int i = threadIdx.y; i < 32; i += 8)
        t[i][threadIdx.x] = W[(long)(k0 + i) * N + n0 + threadIdx.x];
    __syncthreads();
#pragma unroll
    for (int i = threadIdx.y; i < 32; i += 8)
        Wt[(long)(n0 + i) * K + k0 + threadIdx.x] = __float2bfloat16_rn(t[threadIdx.x][i]);
}

// ---------------------------------------------------------------------------
// LayerNorm: warp per row (8 rows / 256-thread block), bf16 output
// (+ optional shift & window partition of SOURCE row)
// ---------------------------------------------------------------------------
__global__ __launch_bounds__(256) void ln_kernel(
    const float* __restrict__ src, const float* __restrict__ gamma,
    const float* __restrict__ beta, __nv_bfloat16* __restrict__ dst, int do_shift)
{
    const int r = blockIdx.x * 8 + (threadIdx.x >> 5);
    const int lane = threadIdx.x & 31;
    long srow = r;
    if (do_shift) {
        int wi = r >> 6, n = r & 63;
        int b  = wi >> 6, wrem = wi & 63;
        int wy = wrem >> 3, wx = wrem & 7;
        int iy = n >> 3,   ix = n & 7;
        int h = (wy * 8 + iy + 4) & 63;
        int w = (wx * 8 + ix + 4) & 63;
        srow = ((long)b * 64 + h) * 64 + w;
    }
    const float* p = src + srow * DIMC;
    float4 v[4];
#pragma unroll
    for (int k = 0; k < 4; k++)
        v[k] = *(const float4*)(p + (k * 32 + lane) * 4);
    float s = 0.f, ss = 0.f;
#pragma unroll
    for (int k = 0; k < 4; k++) {
        s  += v[k].x + v[k].y + v[k].z + v[k].w;
        ss += v[k].x * v[k].x + v[k].y * v[k].y + v[k].z * v[k].z + v[k].w * v[k].w;
    }
#pragma unroll
    for (int o = 16; o; o >>= 1) {
        s  += __shfl_xor_sync(0xffffffffu, s,  o);
        ss += __shfl_xor_sync(0xffffffffu, ss, o);
    }
    float mean = s * (1.0f / 512.0f);
    float var  = ss * (1.0f / 512.0f) - mean * mean;
    float inv  = rsqrtf(var + 1e-5f);
    __nv_bfloat16* drow = dst + (long)r * DIMC;
#pragma unroll
    for (int k = 0; k < 4; k++) {
        int c = (k * 32 + lane) * 4;
        float4 g4 = *(const float4*)(gamma + c);
        float4 b4 = *(const float4*)(beta + c);
        uint2 pk;
        pk.x = pack_bf2((v[k].x - mean) * inv * g4.x + b4.x,
                        (v[k].y - mean) * inv * g4.y + b4.y);
        pk.y = pack_bf2((v[k].z - mean) * inv * g4.z + b4.z,
                        (v[k].w - mean) * inv * g4.w + b4.w);
        *(uint2*)(drow + c) = pk;
    }
}

// ---------------------------------------------------------------------------
// bf16 mma GEMM (identical to R14-passing version)
// ---------------------------------------------------------------------------
#define LDH 40
#define A_HALVES (128 * LDH)
#define STAGE_HALVES (128 * LDH + 128 * LDH)       // 10240 (20480 B)
#define NSTAGE 4
#define GSMEM_BYTES (NSTAGE * STAGE_HALVES * 2)    // 81920
#define LDS 68

__global__ __launch_bounds__(256, 2) void mma_gemm(
    const __nv_bfloat16* __restrict__ A, const __nv_bfloat16* __restrict__ Wt,
    const float* __restrict__ bias, void* __restrict__ Cv,
    int K, int N, int mode, const float* __restrict__ res)
{
    extern __shared__ __align__(16) float sraw[];
    const uint32_t sb = smem_u32(sraw);

    const int tid  = threadIdx.x;
    const int lane = tid & 31;
    const int warp = tid >> 5;
    const int wm   = warp & 3;
    const int wn   = warp >> 2;
    const long brow = (long)blockIdx.y * 128;
    const int  bcol = blockIdx.x * 128;
    const int  Cn = K >> 5;

    const int ar = tid >> 2;
    const int ac = (tid & 3) << 3;

    auto issue_load = [&](int c, int s) {
        const int k0 = c * 32;
        const uint32_t as = sb + (uint32_t)(s * STAGE_HALVES) * 2;
        const uint32_t bs = as + A_HALVES * 2;
#pragma unroll
        for (int i = 0; i < 2; i++) {
            int r = ar + i * 64;
            cp_async16(as + (r * LDH + ac) * 2, A + (brow + r) * (long)K + k0 + ac);
        }
#pragma unroll
        for (int i = 0; i < 2; i++) {
            int r = ar + i * 64;
            cp_async16(bs + (r * LDH + ac) * 2, Wt + (long)(bcol + r) * K + k0 + ac);
        }
        asm volatile("cp.async.commit_group;" ::: "memory");
    };

    float acc[2][8][4];
#pragma unroll
    for (int mt = 0; mt < 2; mt++)
#pragma unroll
        for (int nt = 0; nt < 8; nt++)
#pragma unroll
            for (int q = 0; q < 4; q++) acc[mt][nt][q] = 0.0f;

    const int lrow = (lane & 7) + ((lane >> 3) & 1) * 8;
    const int lcol = (lane >> 4) * 8;

    issue_load(0, 0);
    issue_load(1, 1);
    issue_load(2, 2);

    for (int c = 0; c < Cn; c++) {
        asm volatile("cp.async.wait_group 2;" ::: "memory");
        __syncthreads();
        if (c + NSTAGE - 1 < Cn) issue_load(c + NSTAGE - 1, (c + NSTAGE - 1) % NSTAGE);
        else asm volatile("cp.async.commit_group;" ::: "memory");

        const uint32_t stage = sb + (uint32_t)((c % NSTAGE) * STAGE_HALVES) * 2;
        const uint32_t a_off = stage + ((wm * 32 + lrow) * LDH + lcol) * 2;
        const uint32_t b_off = stage + A_HALVES * 2 + ((wn * 64 + lrow) * LDH + lcol) * 2;
#pragma unroll
        for (int ks = 0; ks < 2; ks++) {
            uint32_t af[2][4], bf[8][2];
#pragma unroll
            for (int mt = 0; mt < 2; mt++)
                ldsm_x4(af[mt][0], af[mt][1], af[mt][2], af[mt][3],
                        a_off + (mt * 16 * LDH + ks * 16) * 2);
#pragma unroll
            for (int np = 0; np < 4; np++) {
                uint32_t r0, r1, r2, r3;
                ldsm_x4(r0, r1, r2, r3, b_off + (np * 16 * LDH + ks * 16) * 2);
                bf[2 * np][0] = r0; bf[2 * np][1] = r2;
                bf[2 * np + 1][0] = r1; bf[2 * np + 1][1] = r3;
            }
#pragma unroll
            for (int mt = 0; mt < 2; mt++)
#pragma unroll
                for (int nt = 0; nt < 8; nt++)
                    mma_bf16(acc[mt][nt], af[mt], bf[nt]);
        }
    }
    asm volatile("cp.async.wait_group 0;" ::: "memory");

    const int gr  = lane >> 2;
    const int tg2 = (lane & 3) * 2;
#pragma unroll 1
    for (int pass = 0; pass < 2; pass++) {
        __syncthreads();
        if (wn == pass) {
#pragma unroll
            for (int mt = 0; mt < 2; mt++)
#pragma unroll
                for (int nt = 0; nt < 8; nt++) {
                    float* st = sraw + (wm * 32 + mt * 16 + gr) * LDS + nt * 8 + tg2;
                    *(float2*)st = make_float2(acc[mt][nt][0], acc[mt][nt][1]);
                    *(float2*)(st + 8 * LDS) = make_float2(acc[mt][nt][2], acc[mt][nt][3]);
                }
        }
        __syncthreads();

        const int r  = tid >> 1;
        const int ch = (tid & 1) * 32;
        long rr = brow + r;
        long orow = rr;
        if (mode == 1) {
            int ri = (int)rr;
            int wi = ri >> 6, n = ri & 63;
            int b  = wi >> 6, wrem = wi & 63;
            int wy = wrem >> 3, wx = wrem & 7;
            int iy = n >> 3,   ix = n & 7;
            int h = (wy * 8 + iy + 4) & 63;
            int w = (wx * 8 + ix + 4) & 63;
            orow = ((long)b * 64 + h) * 64 + w;
        }
        float* crow = (mode == 2) ? nullptr : (float*)Cv + orow * (long)N;
        __nv_bfloat16* crow_bf = (mode == 2)
            ? (__nv_bfloat16*)Cv + orow * (long)N : nullptr;
        const float* rrow = (mode == 1 || mode == 3) ? res + orow * (long)N : nullptr;
#pragma unroll
        for (int j = 0; j < 32; j += 4) {
            int col = bcol + pass * 64 + ch + j;
            float4 v = *(const float4*)(sraw + r * LDS + ch + j);
            float4 b4 = *(const float4*)(bias + col);
            v.x += b4.x; v.y += b4.y; v.z += b4.z; v.w += b4.w;
            if (mode == 2) {
                v.x = 0.5f * v.x * (1.0f + erff(v.x * 0.70710678118654752f));
                v.y = 0.5f * v.y * (1.0f + erff(v.y * 0.70710678118654752f));
                v.z = 0.5f * v.z * (1.0f + erff(v.z * 0.70710678118654752f));
                v.w = 0.5f * v.w * (1.0f + erff(v.w * 0.70710678118654752f));
                uint2 pk;
                pk.x = pack_bf2(v.x, v.y);
                pk.y = pack_bf2(v.z, v.w);
                *(uint2*)(crow_bf + col) = pk;
            } else {
                if (rrow) {
                    float4 r4 = *(const float4*)(rrow + col);
                    v.x += r4.x; v.y += r4.y; v.z += r4.z; v.w += r4.w;
                }
                *(float4*)(crow + col) = v;
            }
        }
    }
}

// ---------------------------------------------------------------------------
// Windowed attention, register-blocked SIMT fp32 (4 rows x 4 cols QK,
// 4 rows x 8 d AV), bf16 output. Same per-output accumulation order as R14.
// ---------------------------------------------------------------------------
#define ATTN_SMEM_FLOATS (64*132 + 128*66 + 64*132 + 64*65 + 240)
#define ATTN_SMEM_BYTES  (ATTN_SMEM_FLOATS * 4)

__global__ __launch_bounds__(256, 1) void attn_kernel(
    const float* __restrict__ qkv, const float* __restrict__ bias_table,
    __nv_bfloat16* __restrict__ out)
{
    extern __shared__ float sm[];
    float* qs = sm;                  // [64][132]  q * scale
    float* kt = qs + 64 * 132;       // [128][66]  k transposed kt[d][m]
    float* vs = kt + 128 * 66;       // [64][132]
    float* at = vs + 64 * 132;       // [64][65]
    float* bt = at + 64 * 65;        // 225 bias values

    const int wi   = blockIdx.x >> 2;
    const int head = blockIdx.x & 3;
    const int tid  = threadIdx.x;
    const float SCALE = 0.08838834764831845f;

    const float* base = qkv + (long)wi * 64 * 1536 + head * 128;
    for (int idx = tid; idx < 64 * 32; idx += 256) {
        int row = idx >> 5;
        int c   = (idx & 31) << 2;
        const float* p = base + (long)row * 1536 + c;
        float4 q4 = *(const float4*)(p);
        float4 k4 = *(const float4*)(p + 512);
        float4 v4 = *(const float4*)(p + 1024);
        qs[row * 132 + c + 0] = q4.x * SCALE;
        qs[row * 132 + c + 1] = q4.y * SCALE;
        qs[row * 132 + c + 2] = q4.z * SCALE;
        qs[row * 132 + c + 3] = q4.w * SCALE;
        kt[(c + 0) * 66 + row] = k4.x;
        kt[(c + 1) * 66 + row] = k4.y;
        kt[(c + 2) * 66 + row] = k4.z;
        kt[(c + 3) * 66 + row] = k4.w;
        vs[row * 132 + c + 0] = v4.x;
        vs[row * 132 + c + 1] = v4.y;
        vs[row * 132 + c + 2] = v4.z;
        vs[row * 132 + c + 3] = v4.w;
    }
    if (tid < 225) bt[tid] = bias_table[tid];
    __syncthreads();

    const int rq = tid >> 4;      // 0..15
    const int cq = tid & 15;      // 0..15
    const int r0 = rq << 2;
    const int c0 = cq << 2;

    // ---- QK^T: 4 rows x 4 cols per thread ----
    float acc[4][4];
#pragma unroll
    for (int i = 0; i < 4; i++)
#pragma unroll
        for (int j = 0; j < 4; j++) acc[i][j] = 0.0f;

#pragma unroll 2
    for (int d = 0; d < 128; d++) {
        float a0 = qs[(r0 + 0) * 132 + d];
        float a1 = qs[(r0 + 1) * 132 + d];
        float a2 = qs[(r0 + 2) * 132 + d];
        float a3 = qs[(r0 + 3) * 132 + d];
        float2 b01 = *(const float2*)&kt[d * 66 + c0];
        float2 b23 = *(const float2*)&kt[d * 66 + c0 + 2];
        float b[4] = {b01.x, b01.y, b23.x, b23.y};
#pragma unroll
        for (int j = 0; j < 4; j++) {
            acc[0][j] = fmaf(a0, b[j], acc[0][j]);
            acc[1][j] = fmaf(a1, b[j], acc[1][j]);
            acc[2][j] = fmaf(a2, b[j], acc[2][j]);
            acc[3][j] = fmaf(a3, b[j], acc[3][j]);
        }
    }

    // ---- bias + softmax (rows r0..r0+3, reduce across 16 lanes) ----
    float mx[4] = {-1e30f, -1e30f, -1e30f, -1e30f};
#pragma unroll
    for (int i = 0; i < 4; i++) {
        int r = r0 + i, ry = r >> 3, rx = r & 7;
#pragma unroll
        for (int j = 0; j < 4; j++) {
            int m = c0 + j;
            acc[i][j] += bt[(ry - (m >> 3) + 7) * 15 + (rx - (m & 7) + 7)];
            mx[i] = fmaxf(mx[i], acc[i][j]);
        }
    }
#pragma unroll
    for (int o = 1; o < 16; o <<= 1)
#pragma unroll
        for (int i = 0; i < 4; i++)
            mx[i] = fmaxf(mx[i], __shfl_xor_sync(0xffffffffu, mx[i], o));
    float sum[4] = {0.f, 0.f, 0.f, 0.f};
#pragma unroll
    for (int i = 0; i < 4; i++)
#pragma unroll
        for (int j = 0; j < 4; j++) {
            acc[i][j] = __expf(acc[i][j] - mx[i]);
            sum[i] += acc[i][j];
        }
#pragma unroll
    for (int o = 1; o < 16; o <<= 1)
#pragma unroll
        for (int i = 0; i < 4; i++)
            sum[i] += __shfl_xor_sync(0xffffffffu, sum[i], o);
#pragma unroll
    for (int i = 0; i < 4; i++) {
        float inv = 1.0f / sum[i];
#pragma unroll
        for (int j = 0; j < 4; j++)
            at[(r0 + i) * 65 + c0 + j] = acc[i][j] * inv;
    }
    __syncwarp();

    // ---- attn @ V: 4 rows x 8 d per thread ----
    const int d0 = cq << 3;   // 0..120
    float o8[4][8];
#pragma unroll
    for (int i = 0; i < 4; i++)
#pragma unroll
        for (int j = 0; j < 8; j++) o8[i][j] = 0.0f;

    for (int m = 0; m < 64; m++) {
        float a0 = at[(r0 + 0) * 65 + m];
        float a1 = at[(r0 + 1) * 65 + m];
        float a2 = at[(r0 + 2) * 65 + m];
        float a3 = at[(r0 + 3) * 65 + m];
        float4 v0 = *(const float4*)&vs[m * 132 + d0];
        float4 v1 = *(const float4*)&vs[m * 132 + d0 + 4];
        float vv[8] = {v0.x, v0.y, v0.z, v0.w, v1.x, v1.y, v1.z, v1.w};
#pragma unroll
        for (int j = 0; j < 8; j++) {
            o8[0][j] = fmaf(a0, vv[j], o8[0][j]);
            o8[1][j] = fmaf(a1, vv[j], o8[1][j]);
            o8[2][j] = fmaf(a2, vv[j], o8[2][j]);
            o8[3][j] = fmaf(a3, vv[j], o8[3][j]);
        }
    }
#pragma unroll
    for (int i = 0; i < 4; i++) {
        __nv_bfloat16* op = out + ((long)(wi * 64 + r0 + i)) * DIMC + head * 128 + d0;
        uint4 pk;
        pk.x = pack_bf2(o8[i][0], o8[i][1]);
        pk.y = pack_bf2(o8[i][2], o8[i][3]);
        pk.z = pack_bf2(o8[i][4], o8[i][5]);
        pk.w = pack_bf2(o8[i][6], o8[i][7]);
        *(uint4*)op = pk;
    }
}

// ---------------------------------------------------------------------------
extern "C" void kernel_launch(void* const* d_in, const int* in_sizes, int n_in,
                              void* d_out, int out_size)
{
    const float* x      = (const float*)d_in[0];
    const float* ln1_g  = (const float*)d_in[1];
    const float* ln1_b  = (const float*)d_in[2];
    const float* qkv_w  = (const float*)d_in[3];
    const float* qkv_b  = (const float*)d_in[4];
    const float* proj_w = (const float*)d_in[5];
    const float* proj_b = (const float*)d_in[6];
    const float* btab   = (const float*)d_in[7];
    const float* ln2_g  = (const float*)d_in[8];
    const float* ln2_b  = (const float*)d_in[9];
    const float* mlp_w1 = (const float*)d_in[10];
    const float* mlp_b1 = (const float*)d_in[11];
    const float* mlp_w2 = (const float*)d_in[12];
    const float* mlp_b2 = (const float*)d_in[13];
    float* outp = (float*)d_out;

    float* S = nullptr;
    cudaGetSymbolAddress((void**)&S, g_scratch);
    __nv_bfloat16* hw   = (__nv_bfloat16*)(S + OFF_HW);
    float*         qkv  = S + OFF_QKV;
    __nv_bfloat16* aout = (__nv_bfloat16*)(S + OFF_AOUT);
    float*         x2   = S + OFF_X2;
    __nv_bfloat16* h2n  = (__nv_bfloat16*)(S + OFF_H2N);
    __nv_bfloat16* m1   = (__nv_bfloat16*)(S + OFF_MLP1);
    __nv_bfloat16* wq   = (__nv_bfloat16*)(S + OFF_WQKV);
    __nv_bfloat16* wp   = (__nv_bfloat16*)(S + OFF_WPROJ);
    __nv_bfloat16* w1   = (__nv_bfloat16*)(S + OFF_WM1);
    __nv_bfloat16* w2   = (__nv_bfloat16*)(S + OFF_WM2);

    cudaFuncSetAttribute(attn_kernel, cudaFuncAttributeMaxDynamicSharedMemorySize,
                         ATTN_SMEM_BYTES);
    cudaFuncSetAttribute(mma_gemm, cudaFuncAttributeMaxDynamicSharedMemorySize,
                         GSMEM_BYTES);

    // transposed bf16 weights [N][K]
    transpose_kernel<<<dim3(48, 16), dim3(32, 8)>>>(qkv_w, wq, 512, 1536);
    transpose_kernel<<<dim3(16, 16), dim3(32, 8)>>>(proj_w, wp, 512, 512);
    transpose_kernel<<<dim3(64, 16), dim3(32, 8)>>>(mlp_w1, w1, 512, 2048);
    transpose_kernel<<<dim3(16, 64), dim3(32, 8)>>>(mlp_w2, w2, 2048, 512);

    // 1) LN1 + cyclic shift + window partition (bf16 out)
    ln_kernel<<<TOKENS / 8, 256>>>(x, ln1_g, ln1_b, hw, 1);
    // 2) QKV GEMM (f32 out)
    mma_gemm<<<dim3(12, 512), 256, GSMEM_BYTES>>>(hw, wq, qkv_b, qkv,
                                                  512, 1536, 0, nullptr);
    // 3) windowed attention (bf16 out)
    attn_kernel<<<NWIN * 4, 256, ATTN_SMEM_BYTES>>>(qkv, btab, aout);
    // 4) proj + window reverse + unshift + residual(x) -> x2 (f32)
    mma_gemm<<<dim3(4, 512), 256, GSMEM_BYTES>>>(aout, wp, proj_b, x2,
                                                 512, 512, 1, x);
    // 5) LN2 (bf16 out)
    ln_kernel<<<TOKENS / 8, 256>>>(x2, ln2_g, ln2_b, h2n, 0);
    // 6) MLP1 + exact GELU (bf16 out)
    mma_gemm<<<dim3(16, 512), 256, GSMEM_BYTES>>>(h2n, w1, mlp_b1, m1,
                                                  512, 2048, 2, nullptr);
    // 7) MLP2 + residual(x2) -> output (f32)
    mma_gemm<<<dim3(4, 512), 256, GSMEM_BYTES>>>(m1, w2, mlp_b2, outp,
                                                 2048, 512, 3, x2);
}

// round 16
// speedup vs baseline: 2.0368x; 1.0436x over previous
#include <cuda_runtime.h>
#include <cuda_bf16.h>
#include <cstdint>

// ---------------------------------------------------------------------------
// Swin Transformer block, bf16 mma.sync m16n8k16 GEMMs (ldmatrix fragments),
// 128x128 CTA tile, 2 CTAs/SM; register-blocked SIMT attention; warp-row LN.
// qkv intermediate in bf16. B=16, H=W=64, C=512, NH=4, WS=8, SS=4
// ---------------------------------------------------------------------------

#define TOKENS   65536
#define DIMC     512
#define NWIN     1024

// scratch layout (float-indexed offsets; bf16 regions reinterpret, use <= half)
#define OFF_HW     0L
#define OFF_QKV    33554432L
#define OFF_AOUT   134217728L
#define OFF_X2     167772160L
#define OFF_H2N    201326592L
#define OFF_MLP1   234881024L
#define OFF_WQKV   369098752L      // transposed bf16 weights [N][K]
#define OFF_WPROJ  369885184L
#define OFF_WM1    370147328L
#define OFF_WM2    371195904L
#define SCRATCH_FLOATS 372244480L

__device__ float g_scratch[SCRATCH_FLOATS];

// ---------------- helpers ----------------
__device__ __forceinline__ uint32_t smem_u32(const void* p) {
    uint32_t a;
    asm("{ .reg .u64 t; cvta.to.shared.u64 t, %1; cvt.u32.u64 %0, t; }" : "=r"(a) : "l"(p));
    return a;
}
__device__ __forceinline__ void cp_async16(uint32_t dst, const void* src) {
    asm volatile("cp.async.cg.shared.global [%0], [%1], 16;" :: "r"(dst), "l"(src));
}
__device__ __forceinline__ void ldsm_x4(uint32_t& r0, uint32_t& r1, uint32_t& r2,
                                        uint32_t& r3, uint32_t addr) {
    asm volatile("ldmatrix.sync.aligned.m8n8.x4.shared.b16 {%0,%1,%2,%3}, [%4];"
                 : "=r"(r0), "=r"(r1), "=r"(r2), "=r"(r3) : "r"(addr));
}
__device__ __forceinline__ void mma_bf16(float* d, const uint32_t* a, const uint32_t* b) {
    asm volatile(
        "mma.sync.aligned.m16n8k16.row.col.f32.bf16.bf16.f32 "
        "{%0,%1,%2,%3}, {%4,%5,%6,%7}, {%8,%9}, {%0,%1,%2,%3};"
        : "+f"(d[0]), "+f"(d[1]), "+f"(d[2]), "+f"(d[3])
        : "r"(a[0]), "r"(a[1]), "r"(a[2]), "r"(a[3]), "r"(b[0]), "r"(b[1]));
}
__device__ __forceinline__ uint32_t pack_bf2(float x, float y) {
    __nv_bfloat162 p = __float22bfloat162_rn(make_float2(x, y));
    return *(uint32_t*)&p;
}

// ---------------------------------------------------------------------------
// Weight transpose [K,N] -> [N,K], bf16
// ---------------------------------------------------------------------------
__global__ __launch_bounds__(256) void transpose_kernel(
    const float* __restrict__ W, __nv_bfloat16* __restrict__ Wt, int K, int N)
{
    __shared__ float t[32][33];
    int n0 = blockIdx.x * 32, k0 = blockIdx.y * 32;
#pragma unroll
    for (int i = threadIdx.y; i < 32; i += 8)
        t[i][threadIdx.x] = W[(long)(k0 + i) * N + n0 + threadIdx.x];
    __syncthreads();
#pragma unroll
    for (int i = threadIdx.y; i < 32; i += 8)
        Wt[(long)(n0 + i) * K + k0 + threadIdx.x] = __float2bfloat16_rn(t[threadIdx.x][i]);
}

// ---------------------------------------------------------------------------
// LayerNorm: warp per row (8 rows / 256-thread block), bf16 output
// (+ optional shift & window partition of SOURCE row)
// ---------------------------------------------------------------------------
__global__ __launch_bounds__(256) void ln_kernel(
    const float* __restrict__ src, const float* __restrict__ gamma,
    const float* __restrict__ beta, __nv_bfloat16* __restrict__ dst, int do_shift)
{
    const int r = blockIdx.x * 8 + (threadIdx.x >> 5);
    const int lane = threadIdx.x & 31;
    long srow = r;
    if (do_shift) {
        int wi = r >> 6, n = r & 63;
        int b  = wi >> 6, wrem = wi & 63;
        int wy = wrem >> 3, wx = wrem & 7;
        int iy = n >> 3,   ix = n & 7;
        int h = (wy * 8 + iy + 4) & 63;
        int w = (wx * 8 + ix + 4) & 63;
        srow = ((long)b * 64 + h) * 64 + w;
    }
    const float* p = src + srow * DIMC;
    float4 v[4];
#pragma unroll
    for (int k = 0; k < 4; k++)
        v[k] = *(const float4*)(p + (k * 32 + lane) * 4);
    float s = 0.f, ss = 0.f;
#pragma unroll
    for (int k = 0; k < 4; k++) {
        s  += v[k].x + v[k].y + v[k].z + v[k].w;
        ss += v[k].x * v[k].x + v[k].y * v[k].y + v[k].z * v[k].z + v[k].w * v[k].w;
    }
#pragma unroll
    for (int o = 16; o; o >>= 1) {
        s  += __shfl_xor_sync(0xffffffffu, s,  o);
        ss += __shfl_xor_sync(0xffffffffu, ss, o);
    }
    float mean = s * (1.0f / 512.0f);
    float var  = ss * (1.0f / 512.0f) - mean * mean;
    float inv  = rsqrtf(var + 1e-5f);
    __nv_bfloat16* drow = dst + (long)r * DIMC;
#pragma unroll
    for (int k = 0; k < 4; k++) {
        int c = (k * 32 + lane) * 4;
        float4 g4 = *(const float4*)(gamma + c);
        float4 b4 = *(const float4*)(beta + c);
        uint2 pk;
        pk.x = pack_bf2((v[k].x - mean) * inv * g4.x + b4.x,
                        (v[k].y - mean) * inv * g4.y + b4.y);
        pk.y = pack_bf2((v[k].z - mean) * inv * g4.z + b4.z,
                        (v[k].w - mean) * inv * g4.w + b4.w);
        *(uint2*)(drow + c) = pk;
    }
}

// ---------------------------------------------------------------------------
// bf16 mma GEMM: C[M,N] = A[M,K] @ Wt[N,K]^T   (A, Wt bf16; acc fp32)
// CTA tile 128x128, BK=32 halves, 4-stage cp.async, 2 CTAs/SM,
// 8 warps (4m x 2n), warp tile 32x64.
// modes: 0 bias(bf16 out) | 1 bias+winrev+residual(f32) | 2 bias+GELU(bf16 out)
//        | 3 bias+residual(f32)
// ---------------------------------------------------------------------------
#define LDH 40
#define A_HALVES (128 * LDH)
#define STAGE_HALVES (128 * LDH + 128 * LDH)       // 10240 (20480 B)
#define NSTAGE 4
#define GSMEM_BYTES (NSTAGE * STAGE_HALVES * 2)    // 81920
#define LDS 68

__global__ __launch_bounds__(256, 2) void mma_gemm(
    const __nv_bfloat16* __restrict__ A, const __nv_bfloat16* __restrict__ Wt,
    const float* __restrict__ bias, void* __restrict__ Cv,
    int K, int N, int mode, const float* __restrict__ res)
{
    extern __shared__ __align__(16) float sraw[];
    const uint32_t sb = smem_u32(sraw);

    const int tid  = threadIdx.x;
    const int lane = tid & 31;
    const int warp = tid >> 5;
    const int wm   = warp & 3;
    const int wn   = warp >> 2;
    const long brow = (long)blockIdx.y * 128;
    const int  bcol = blockIdx.x * 128;
    const int  Cn = K >> 5;

    const int ar = tid >> 2;
    const int ac = (tid & 3) << 3;

    auto issue_load = [&](int c, int s) {
        const int k0 = c * 32;
        const uint32_t as = sb + (uint32_t)(s * STAGE_HALVES) * 2;
        const uint32_t bs = as + A_HALVES * 2;
#pragma unroll
        for (int i = 0; i < 2; i++) {
            int r = ar + i * 64;
            cp_async16(as + (r * LDH + ac) * 2, A + (brow + r) * (long)K + k0 + ac);
        }
#pragma unroll
        for (int i = 0; i < 2; i++) {
            int r = ar + i * 64;
            cp_async16(bs + (r * LDH + ac) * 2, Wt + (long)(bcol + r) * K + k0 + ac);
        }
        asm volatile("cp.async.commit_group;" ::: "memory");
    };

    float acc[2][8][4];
#pragma unroll
    for (int mt = 0; mt < 2; mt++)
#pragma unroll
        for (int nt = 0; nt < 8; nt++)
#pragma unroll
            for (int q = 0; q < 4; q++) acc[mt][nt][q] = 0.0f;

    const int lrow = (lane & 7) + ((lane >> 3) & 1) * 8;
    const int lcol = (lane >> 4) * 8;

    issue_load(0, 0);
    issue_load(1, 1);
    issue_load(2, 2);

    for (int c = 0; c < Cn; c++) {
        asm volatile("cp.async.wait_group 2;" ::: "memory");
        __syncthreads();
        if (c + NSTAGE - 1 < Cn) issue_load(c + NSTAGE - 1, (c + NSTAGE - 1) % NSTAGE);
        else asm volatile("cp.async.commit_group;" ::: "memory");

        const uint32_t stage = sb + (uint32_t)((c % NSTAGE) * STAGE_HALVES) * 2;
        const uint32_t a_off = stage + ((wm * 32 + lrow) * LDH + lcol) * 2;
        const uint32_t b_off = stage + A_HALVES * 2 + ((wn * 64 + lrow) * LDH + lcol) * 2;
#pragma unroll
        for (int ks = 0; ks < 2; ks++) {
            uint32_t af[2][4], bf[8][2];
#pragma unroll
            for (int mt = 0; mt < 2; mt++)
                ldsm_x4(af[mt][0], af[mt][1], af[mt][2], af[mt][3],
                        a_off + (mt * 16 * LDH + ks * 16) * 2);
#pragma unroll
            for (int np = 0; np < 4; np++) {
                uint32_t r0, r1, r2, r3;
                ldsm_x4(r0, r1, r2, r3, b_off + (np * 16 * LDH + ks * 16) * 2);
                bf[2 * np][0] = r0; bf[2 * np][1] = r2;
                bf[2 * np + 1][0] = r1; bf[2 * np + 1][1] = r3;
            }
#pragma unroll
            for (int mt = 0; mt < 2; mt++)
#pragma unroll
                for (int nt = 0; nt < 8; nt++)
                    mma_bf16(acc[mt][nt], af[mt], bf[nt]);
        }
    }
    asm volatile("cp.async.wait_group 0;" ::: "memory");

    const int gr  = lane >> 2;
    const int tg2 = (lane & 3) * 2;
#pragma unroll 1
    for (int pass = 0; pass < 2; pass++) {
        __syncthreads();
        if (wn == pass) {
#pragma unroll
            for (int mt = 0; mt < 2; mt++)
#pragma unroll
                for (int nt = 0; nt < 8; nt++) {
                    float* st = sraw + (wm * 32 + mt * 16 + gr) * LDS + nt * 8 + tg2;
                    *(float2*)st = make_float2(acc[mt][nt][0], acc[mt][nt][1]);
                    *(float2*)(st + 8 * LDS) = make_float2(acc[mt][nt][2], acc[mt][nt][3]);
                }
        }
        __syncthreads();

        const int r  = tid >> 1;
        const int ch = (tid & 1) * 32;
        long rr = brow + r;
        long orow = rr;
        if (mode == 1) {
            int ri = (int)rr;
            int wi = ri >> 6, n = ri & 63;
            int b  = wi >> 6, wrem = wi & 63;
            int wy = wrem >> 3, wx = wrem & 7;
            int iy = n >> 3,   ix = n & 7;
            int h = (wy * 8 + iy + 4) & 63;
            int w = (wx * 8 + ix + 4) & 63;
            orow = ((long)b * 64 + h) * 64 + w;
        }
        const int bf16_out = (mode == 0 || mode == 2);
        float* crow = bf16_out ? nullptr : (float*)Cv + orow * (long)N;
        __nv_bfloat16* crow_bf = bf16_out
            ? (__nv_bfloat16*)Cv + orow * (long)N : nullptr;
        const float* rrow = (mode == 1 || mode == 3) ? res + orow * (long)N : nullptr;
#pragma unroll
        for (int j = 0; j < 32; j += 4) {
            int col = bcol + pass * 64 + ch + j;
            float4 v = *(const float4*)(sraw + r * LDS + ch + j);
            float4 b4 = *(const float4*)(bias + col);
            v.x += b4.x; v.y += b4.y; v.z += b4.z; v.w += b4.w;
            if (bf16_out) {
                if (mode == 2) {
                    v.x = 0.5f * v.x * (1.0f + erff(v.x * 0.70710678118654752f));
                    v.y = 0.5f * v.y * (1.0f + erff(v.y * 0.70710678118654752f));
                    v.z = 0.5f * v.z * (1.0f + erff(v.z * 0.70710678118654752f));
                    v.w = 0.5f * v.w * (1.0f + erff(v.w * 0.70710678118654752f));
                }
                uint2 pk;
                pk.x = pack_bf2(v.x, v.y);
                pk.y = pack_bf2(v.z, v.w);
                *(uint2*)(crow_bf + col) = pk;
            } else {
                if (rrow) {
                    float4 r4 = *(const float4*)(rrow + col);
                    v.x += r4.x; v.y += r4.y; v.z += r4.z; v.w += r4.w;
                }
                *(float4*)(crow + col) = v;
            }
        }
    }
}

// ---------------------------------------------------------------------------
// Windowed attention, register-blocked SIMT fp32, bf16 qkv input, bf16 output.
// ---------------------------------------------------------------------------
#define ATTN_SMEM_FLOATS (64*132 + 128*66 + 64*132 + 64*65 + 240)
#define ATTN_SMEM_BYTES  (ATTN_SMEM_FLOATS * 4)

__global__ __launch_bounds__(256, 1) void attn_kernel(
    const __nv_bfloat16* __restrict__ qkv, const float* __restrict__ bias_table,
    __nv_bfloat16* __restrict__ out)
{
    extern __shared__ float sm[];
    float* qs = sm;                  // [64][132]  q * scale
    float* kt = qs + 64 * 132;       // [128][66]  k transposed kt[d][m]
    float* vs = kt + 128 * 66;       // [64][132]
    float* at = vs + 64 * 132;       // [64][65]
    float* bt = at + 64 * 65;        // 225 bias values

    const int wi   = blockIdx.x >> 2;
    const int head = blockIdx.x & 3;
    const int tid  = threadIdx.x;
    const float SCALE = 0.08838834764831845f;

    const __nv_bfloat16* base = qkv + (long)wi * 64 * 1536 + head * 128;
    for (int idx = tid; idx < 64 * 16; idx += 256) {
        int row = idx >> 4;
        int c   = (idx & 15) << 3;       // 0..120 step 8
        const __nv_bfloat16* p = base + (long)row * 1536 + c;
        uint4 qa = *(const uint4*)(p);
        uint4 ka = *(const uint4*)(p + 512);
        uint4 va = *(const uint4*)(p + 1024);
        const uint32_t qw[4] = {qa.x, qa.y, qa.z, qa.w};
        const uint32_t kw[4] = {ka.x, ka.y, ka.z, ka.w};
        const uint32_t vw[4] = {va.x, va.y, va.z, va.w};
#pragma unroll
        for (int j = 0; j < 4; j++) {
            float2 qf = __bfloat1622float2(*(const __nv_bfloat162*)&qw[j]);
            float2 kf = __bfloat1622float2(*(const __nv_bfloat162*)&kw[j]);
            float2 vf = __bfloat1622float2(*(const __nv_bfloat162*)&vw[j]);
            int cc = c + 2 * j;
            qs[row * 132 + cc]     = qf.x * SCALE;
            qs[row * 132 + cc + 1] = qf.y * SCALE;
            kt[(cc)     * 66 + row] = kf.x;
            kt[(cc + 1) * 66 + row] = kf.y;
            vs[row * 132 + cc]     = vf.x;
            vs[row * 132 + cc + 1] = vf.y;
        }
    }
    if (tid < 225) bt[tid] = bias_table[tid];
    __syncthreads();

    const int rq = tid >> 4;      // 0..15
    const int cq = tid & 15;      // 0..15
    const int r0 = rq << 2;
    const int c0 = cq << 2;

    // ---- QK^T: 4 rows x 4 cols per thread ----
    float acc[4][4];
#pragma unroll
    for (int i = 0; i < 4; i++)
#pragma unroll
        for (int j = 0; j < 4; j++) acc[i][j] = 0.0f;

#pragma unroll 2
    for (int d = 0; d < 128; d++) {
        float a0 = qs[(r0 + 0) * 132 + d];
        float a1 = qs[(r0 + 1) * 132 + d];
        float a2 = qs[(r0 + 2) * 132 + d];
        float a3 = qs[(r0 + 3) * 132 + d];
        float2 b01 = *(const float2*)&kt[d * 66 + c0];
        float2 b23 = *(const float2*)&kt[d * 66 + c0 + 2];
        float b[4] = {b01.x, b01.y, b23.x, b23.y};
#pragma unroll
        for (int j = 0; j < 4; j++) {
            acc[0][j] = fmaf(a0, b[j], acc[0][j]);
            acc[1][j] = fmaf(a1, b[j], acc[1][j]);
            acc[2][j] = fmaf(a2, b[j], acc[2][j]);
            acc[3][j] = fmaf(a3, b[j], acc[3][j]);
        }
    }

    // ---- bias + softmax (rows r0..r0+3, reduce across 16 lanes) ----
    float mx[4] = {-1e30f, -1e30f, -1e30f, -1e30f};
#pragma unroll
    for (int i = 0; i < 4; i++) {
        int r = r0 + i, ry = r >> 3, rx = r & 7;
#pragma unroll
        for (int j = 0; j < 4; j++) {
            int m = c0 + j;
            acc[i][j] += bt[(ry - (m >> 3) + 7) * 15 + (rx - (m & 7) + 7)];
            mx[i] = fmaxf(mx[i], acc[i][j]);
        }
    }
#pragma unroll
    for (int o = 1; o < 16; o <<= 1)
#pragma unroll
        for (int i = 0; i < 4; i++)
            mx[i] = fmaxf(mx[i], __shfl_xor_sync(0xffffffffu, mx[i], o));
    float sum[4] = {0.f, 0.f, 0.f, 0.f};
#pragma unroll
    for (int i = 0; i < 4; i++)
#pragma unroll
        for (int j = 0; j < 4; j++) {
            acc[i][j] = __expf(acc[i][j] - mx[i]);
            sum[i] += acc[i][j];
        }
#pragma unroll
    for (int o = 1; o < 16; o <<= 1)
#pragma unroll
        for (int i = 0; i < 4; i++)
            sum[i] += __shfl_xor_sync(0xffffffffu, sum[i], o);
#pragma unroll
    for (int i = 0; i < 4; i++) {
        float inv = 1.0f / sum[i];
#pragma unroll
        for (int j = 0; j < 4; j++)
            at[(r0 + i) * 65 + c0 + j] = acc[i][j] * inv;
    }
    __syncwarp();

    // ---- attn @ V: 4 rows x 8 d per thread ----
    const int d0 = cq << 3;   // 0..120
    float o8[4][8];
#pragma unroll
    for (int i = 0; i < 4; i++)
#pragma unroll
        for (int j = 0; j < 8; j++) o8[i][j] = 0.0f;

    for (int m = 0; m < 64; m++) {
        float a0 = at[(r0 + 0) * 65 + m];
        float a1 = at[(r0 + 1) * 65 + m];
        float a2 = at[(r0 + 2) * 65 + m];
        float a3 = at[(r0 + 3) * 65 + m];
        float4 v0 = *(const float4*)&vs[m * 132 + d0];
        float4 v1 = *(const float4*)&vs[m * 132 + d0 + 4];
        float vv[8] = {v0.x, v0.y, v0.z, v0.w, v1.x, v1.y, v1.z, v1.w};
#pragma unroll
        for (int j = 0; j < 8; j++) {
            o8[0][j] = fmaf(a0, vv[j], o8[0][j]);
            o8[1][j] = fmaf(a1, vv[j], o8[1][j]);
            o8[2][j] = fmaf(a2, vv[j], o8[2][j]);
            o8[3][j] = fmaf(a3, vv[j], o8[3][j]);
        }
    }
#pragma unroll
    for (int i = 0; i < 4; i++) {
        __nv_bfloat16* op = out + ((long)(wi * 64 + r0 + i)) * DIMC + head * 128 + d0;
        uint4 pk;
        pk.x = pack_bf2(o8[i][0], o8[i][1]);
        pk.y = pack_bf2(o8[i][2], o8[i][3]);
        pk.z = pack_bf2(o8[i][4], o8[i][5]);
        pk.w = pack_bf2(o8[i][6], o8[i][7]);
        *(uint4*)op = pk;
    }
}

// ---------------------------------------------------------------------------
extern "C" void kernel_launch(void* const* d_in, const int* in_sizes, int n_in,
                              void* d_out, int out_size)
{
    const float* x      = (const float*)d_in[0];
    const float* ln1_g  = (const float*)d_in[1];
    const float* ln1_b  = (const float*)d_in[2];
    const float* qkv_w  = (const float*)d_in[3];
    const float* qkv_b  = (const float*)d_in[4];
    const float* proj_w = (const float*)d_in[5];
    const float* proj_b = (const float*)d_in[6];
    const float* btab   = (const float*)d_in[7];
    const float* ln2_g  = (const float*)d_in[8];
    const float* ln2_b  = (const float*)d_in[9];
    const float* mlp_w1 = (const float*)d_in[10];
    const float* mlp_b1 = (const float*)d_in[11];
    const float* mlp_w2 = (const float*)d_in[12];
    const float* mlp_b2 = (const float*)d_in[13];
    float* outp = (float*)d_out;

    float* S = nullptr;
    cudaGetSymbolAddress((void**)&S, g_scratch);
    __nv_bfloat16* hw   = (__nv_bfloat16*)(S + OFF_HW);
    __nv_bfloat16* qkv  = (__nv_bfloat16*)(S + OFF_QKV);
    __nv_bfloat16* aout = (__nv_bfloat16*)(S + OFF_AOUT);
    float*         x2   = S + OFF_X2;
    __nv_bfloat16* h2n  = (__nv_bfloat16*)(S + OFF_H2N);
    __nv_bfloat16* m1   = (__nv_bfloat16*)(S + OFF_MLP1);
    __nv_bfloat16* wq   = (__nv_bfloat16*)(S + OFF_WQKV);
    __nv_bfloat16* wp   = (__nv_bfloat16*)(S + OFF_WPROJ);
    __nv_bfloat16* w1   = (__nv_bfloat16*)(S + OFF_WM1);
    __nv_bfloat16* w2   = (__nv_bfloat16*)(S + OFF_WM2);

    cudaFuncSetAttribute(attn_kernel, cudaFuncAttributeMaxDynamicSharedMemorySize,
                         ATTN_SMEM_BYTES);
    cudaFuncSetAttribute(mma_gemm, cudaFuncAttributeMaxDynamicSharedMemorySize,
                         GSMEM_BYTES);

    // transposed bf16 weights [N][K]
    transpose_kernel<<<dim3(48, 16), dim3(32, 8)>>>(qkv_w, wq, 512, 1536);
    transpose_kernel<<<dim3(16, 16), dim3(32, 8)>>>(proj_w, wp, 512, 512);
    transpose_kernel<<<dim3(64, 16), dim3(32, 8)>>>(mlp_w1, w1, 512, 2048);
    transpose_kernel<<<dim3(16, 64), dim3(32, 8)>>>(mlp_w2, w2, 2048, 512);

    // 1) LN1 + cyclic shift + window partition (bf16 out)
    ln_kernel<<<TOKENS / 8, 256>>>(x, ln1_g, ln1_b, hw, 1);
    // 2) QKV GEMM (bf16 out)
    mma_gemm<<<dim3(12, 512), 256, GSMEM_BYTES>>>(hw, wq, qkv_b, qkv,
                                                  512, 1536, 0, nullptr);
    // 3) windowed attention (bf16 out)
    attn_kernel<<<NWIN * 4, 256, ATTN_SMEM_BYTES>>>(qkv, btab, aout);
    // 4) proj + window reverse + unshift + residual(x) -> x2 (f32)
    mma_gemm<<<dim3(4, 512), 256, GSMEM_BYTES>>>(aout, wp, proj_b, x2,
                                                 512, 512, 1, x);
    // 5) LN2 (bf16 out)
    ln_kernel<<<TOKENS / 8, 256>>>(x2, ln2_g, ln2_b, h2n, 0);
    // 6) MLP1 + exact GELU (bf16 out)
    mma_gemm<<<dim3(16, 512), 256, GSMEM_BYTES>>>(h2n, w1, mlp_b1, m1,
                                                  512, 2048, 2, nullptr);
    // 7) MLP2 + residual(x2) -> output (f32)
    mma_gemm<<<dim3(4, 512), 256, GSMEM_BYTES>>>(m1, w2, mlp_b2, outp,
                                                 2048, 512, 3, x2);
}

// round 17
// speedup vs baseline: 2.1163x; 1.0391x over previous
#include <cuda_runtime.h>
#include <cuda_bf16.h>
#include <cstdint>

// ---------------------------------------------------------------------------
// Swin Transformer block, bf16 mma.sync m16n8k16 GEMMs (ldmatrix fragments),
// 128x128 CTA tile, 2 CTAs/SM; register-blocked SIMT attention with bf16 smem
// tiles (2 CTAs/SM); warp-row LN. qkv intermediate in bf16.
// B=16, H=W=64, C=512, NH=4, WS=8, SS=4
// ---------------------------------------------------------------------------

#define TOKENS   65536
#define DIMC     512
#define NWIN     1024

// scratch layout (float-indexed offsets; bf16 regions reinterpret, use <= half)
#define OFF_HW     0L
#define OFF_QKV    33554432L
#define OFF_AOUT   134217728L
#define OFF_X2     167772160L
#define OFF_H2N    201326592L
#define OFF_MLP1   234881024L
#define OFF_WQKV   369098752L      // transposed bf16 weights [N][K]
#define OFF_WPROJ  369885184L
#define OFF_WM1    370147328L
#define OFF_WM2    371195904L
#define SCRATCH_FLOATS 372244480L

__device__ float g_scratch[SCRATCH_FLOATS];

// ---------------- helpers ----------------
__device__ __forceinline__ uint32_t smem_u32(const void* p) {
    uint32_t a;
    asm("{ .reg .u64 t; cvta.to.shared.u64 t, %1; cvt.u32.u64 %0, t; }" : "=r"(a) : "l"(p));
    return a;
}
__device__ __forceinline__ void cp_async16(uint32_t dst, const void* src) {
    asm volatile("cp.async.cg.shared.global [%0], [%1], 16;" :: "r"(dst), "l"(src));
}
__device__ __forceinline__ void ldsm_x4(uint32_t& r0, uint32_t& r1, uint32_t& r2,
                                        uint32_t& r3, uint32_t addr) {
    asm volatile("ldmatrix.sync.aligned.m8n8.x4.shared.b16 {%0,%1,%2,%3}, [%4];"
                 : "=r"(r0), "=r"(r1), "=r"(r2), "=r"(r3) : "r"(addr));
}
__device__ __forceinline__ void mma_bf16(float* d, const uint32_t* a, const uint32_t* b) {
    asm volatile(
        "mma.sync.aligned.m16n8k16.row.col.f32.bf16.bf16.f32 "
        "{%0,%1,%2,%3}, {%4,%5,%6,%7}, {%8,%9}, {%0,%1,%2,%3};"
        : "+f"(d[0]), "+f"(d[1]), "+f"(d[2]), "+f"(d[3])
        : "r"(a[0]), "r"(a[1]), "r"(a[2]), "r"(a[3]), "r"(b[0]), "r"(b[1]));
}
__device__ __forceinline__ uint32_t pack_bf2(float x, float y) {
    __nv_bfloat162 p = __float22bfloat162_rn(make_float2(x, y));
    return *(uint32_t*)&p;
}

// ---------------------------------------------------------------------------
// Weight transpose [K,N] -> [N,K], bf16
// ---------------------------------------------------------------------------
__global__ __launch_bounds__(256) void transpose_kernel(
    const float* __restrict__ W, __nv_bfloat16* __restrict__ Wt, int K, int N)
{
    __shared__ float t[32][33];
    int n0 = blockIdx.x * 32, k0 = blockIdx.y * 32;
#pragma unroll
    for (int i = threadIdx.y; i < 32; i += 8)
        t[i][threadIdx.x] = W[(long)(k0 + i) * N + n0 + threadIdx.x];
    __syncthreads();
#pragma unroll
    for (int i = threadIdx.y; i < 32; i += 8)
        Wt[(long)(n0 + i) * K + k0 + threadIdx.x] = __float2bfloat16_rn(t[threadIdx.x][i]);
}

// ---------------------------------------------------------------------------
// LayerNorm: warp per row (8 rows / 256-thread block), bf16 output
// (+ optional shift & window partition of SOURCE row)
// ---------------------------------------------------------------------------
__global__ __launch_bounds__(256) void ln_kernel(
    const float* __restrict__ src, const float* __restrict__ gamma,
    const float* __restrict__ beta, __nv_bfloat16* __restrict__ dst, int do_shift)
{
    const int r = blockIdx.x * 8 + (threadIdx.x >> 5);
    const int lane = threadIdx.x & 31;
    long srow = r;
    if (do_shift) {
        int wi = r >> 6, n = r & 63;
        int b  = wi >> 6, wrem = wi & 63;
        int wy = wrem >> 3, wx = wrem & 7;
        int iy = n >> 3,   ix = n & 7;
        int h = (wy * 8 + iy + 4) & 63;
        int w = (wx * 8 + ix + 4) & 63;
        srow = ((long)b * 64 + h) * 64 + w;
    }
    const float* p = src + srow * DIMC;
    float4 v[4];
#pragma unroll
    for (int k = 0; k < 4; k++)
        v[k] = *(const float4*)(p + (k * 32 + lane) * 4);
    float s = 0.f, ss = 0.f;
#pragma unroll
    for (int k = 0; k < 4; k++) {
        s  += v[k].x + v[k].y + v[k].z + v[k].w;
        ss += v[k].x * v[k].x + v[k].y * v[k].y + v[k].z * v[k].z + v[k].w * v[k].w;
    }
#pragma unroll
    for (int o = 16; o; o >>= 1) {
        s  += __shfl_xor_sync(0xffffffffu, s,  o);
        ss += __shfl_xor_sync(0xffffffffu, ss, o);
    }
    float mean = s * (1.0f / 512.0f);
    float var  = ss * (1.0f / 512.0f) - mean * mean;
    float inv  = rsqrtf(var + 1e-5f);
    __nv_bfloat16* drow = dst + (long)r * DIMC;
#pragma unroll
    for (int k = 0; k < 4; k++) {
        int c = (k * 32 + lane) * 4;
        float4 g4 = *(const float4*)(gamma + c);
        float4 b4 = *(const float4*)(beta + c);
        uint2 pk;
        pk.x = pack_bf2((v[k].x - mean) * inv * g4.x + b4.x,
                        (v[k].y - mean) * inv * g4.y + b4.y);
        pk.y = pack_bf2((v[k].z - mean) * inv * g4.z + b4.z,
                        (v[k].w - mean) * inv * g4.w + b4.w);
        *(uint2*)(drow + c) = pk;
    }
}

// ---------------------------------------------------------------------------
// bf16 mma GEMM (identical to R16-passing version)
// ---------------------------------------------------------------------------
#define LDH 40
#define A_HALVES (128 * LDH)
#define STAGE_HALVES (128 * LDH + 128 * LDH)       // 10240 (20480 B)
#define NSTAGE 4
#define GSMEM_BYTES (NSTAGE * STAGE_HALVES * 2)    // 81920
#define LDS 68

__global__ __launch_bounds__(256, 2) void mma_gemm(
    const __nv_bfloat16* __restrict__ A, const __nv_bfloat16* __restrict__ Wt,
    const float* __restrict__ bias, void* __restrict__ Cv,
    int K, int N, int mode, const float* __restrict__ res)
{
    extern __shared__ __align__(16) float sraw[];
    const uint32_t sb = smem_u32(sraw);

    const int tid  = threadIdx.x;
    const int lane = tid & 31;
    const int warp = tid >> 5;
    const int wm   = warp & 3;
    const int wn   = warp >> 2;
    const long brow = (long)blockIdx.y * 128;
    const int  bcol = blockIdx.x * 128;
    const int  Cn = K >> 5;

    const int ar = tid >> 2;
    const int ac = (tid & 3) << 3;

    auto issue_load = [&](int c, int s) {
        const int k0 = c * 32;
        const uint32_t as = sb + (uint32_t)(s * STAGE_HALVES) * 2;
        const uint32_t bs = as + A_HALVES * 2;
#pragma unroll
        for (int i = 0; i < 2; i++) {
            int r = ar + i * 64;
            cp_async16(as + (r * LDH + ac) * 2, A + (brow + r) * (long)K + k0 + ac);
        }
#pragma unroll
        for (int i = 0; i < 2; i++) {
            int r = ar + i * 64;
            cp_async16(bs + (r * LDH + ac) * 2, Wt + (long)(bcol + r) * K + k0 + ac);
        }
        asm volatile("cp.async.commit_group;" ::: "memory");
    };

    float acc[2][8][4];
#pragma unroll
    for (int mt = 0; mt < 2; mt++)
#pragma unroll
        for (int nt = 0; nt < 8; nt++)
#pragma unroll
            for (int q = 0; q < 4; q++) acc[mt][nt][q] = 0.0f;

    const int lrow = (lane & 7) + ((lane >> 3) & 1) * 8;
    const int lcol = (lane >> 4) * 8;

    issue_load(0, 0);
    issue_load(1, 1);
    issue_load(2, 2);

    for (int c = 0; c < Cn; c++) {
        asm volatile("cp.async.wait_group 2;" ::: "memory");
        __syncthreads();
        if (c + NSTAGE - 1 < Cn) issue_load(c + NSTAGE - 1, (c + NSTAGE - 1) % NSTAGE);
        else asm volatile("cp.async.commit_group;" ::: "memory");

        const uint32_t stage = sb + (uint32_t)((c % NSTAGE) * STAGE_HALVES) * 2;
        const uint32_t a_off = stage + ((wm * 32 + lrow) * LDH + lcol) * 2;
        const uint32_t b_off = stage + A_HALVES * 2 + ((wn * 64 + lrow) * LDH + lcol) * 2;
#pragma unroll
        for (int ks = 0; ks < 2; ks++) {
            uint32_t af[2][4], bf[8][2];
#pragma unroll
            for (int mt = 0; mt < 2; mt++)
                ldsm_x4(af[mt][0], af[mt][1], af[mt][2], af[mt][3],
                        a_off + (mt * 16 * LDH + ks * 16) * 2);
#pragma unroll
            for (int np = 0; np < 4; np++) {
                uint32_t r0, r1, r2, r3;
                ldsm_x4(r0, r1, r2, r3, b_off + (np * 16 * LDH + ks * 16) * 2);
                bf[2 * np][0] = r0; bf[2 * np][1] = r2;
                bf[2 * np + 1][0] = r1; bf[2 * np + 1][1] = r3;
            }
#pragma unroll
            for (int mt = 0; mt < 2; mt++)
#pragma unroll
                for (int nt = 0; nt < 8; nt++)
                    mma_bf16(acc[mt][nt], af[mt], bf[nt]);
        }
    }
    asm volatile("cp.async.wait_group 0;" ::: "memory");

    const int gr  = lane >> 2;
    const int tg2 = (lane & 3) * 2;
#pragma unroll 1
    for (int pass = 0; pass < 2; pass++) {
        __syncthreads();
        if (wn == pass) {
#pragma unroll
            for (int mt = 0; mt < 2; mt++)
#pragma unroll
                for (int nt = 0; nt < 8; nt++) {
                    float* st = sraw + (wm * 32 + mt * 16 + gr) * LDS + nt * 8 + tg2;
                    *(float2*)st = make_float2(acc[mt][nt][0], acc[mt][nt][1]);
                    *(float2*)(st + 8 * LDS) = make_float2(acc[mt][nt][2], acc[mt][nt][3]);
                }
        }
        __syncthreads();

        const int r  = tid >> 1;
        const int ch = (tid & 1) * 32;
        long rr = brow + r;
        long orow = rr;
        if (mode == 1) {
            int ri = (int)rr;
            int wi = ri >> 6, n = ri & 63;
            int b  = wi >> 6, wrem = wi & 63;
            int wy = wrem >> 3, wx = wrem & 7;
            int iy = n >> 3,   ix = n & 7;
            int h = (wy * 8 + iy + 4) & 63;
            int w = (wx * 8 + ix + 4) & 63;
            orow = ((long)b * 64 + h) * 64 + w;
        }
        const int bf16_out = (mode == 0 || mode == 2);
        float* crow = bf16_out ? nullptr : (float*)Cv + orow * (long)N;
        __nv_bfloat16* crow_bf = bf16_out
            ? (__nv_bfloat16*)Cv + orow * (long)N : nullptr;
        const float* rrow = (mode == 1 || mode == 3) ? res + orow * (long)N : nullptr;
#pragma unroll
        for (int j = 0; j < 32; j += 4) {
            int col = bcol + pass * 64 + ch + j;
            float4 v = *(const float4*)(sraw + r * LDS + ch + j);
            float4 b4 = *(const float4*)(bias + col);
            v.x += b4.x; v.y += b4.y; v.z += b4.z; v.w += b4.w;
            if (bf16_out) {
                if (mode == 2) {
                    v.x = 0.5f * v.x * (1.0f + erff(v.x * 0.70710678118654752f));
                    v.y = 0.5f * v.y * (1.0f + erff(v.y * 0.70710678118654752f));
                    v.z = 0.5f * v.z * (1.0f + erff(v.z * 0.70710678118654752f));
                    v.w = 0.5f * v.w * (1.0f + erff(v.w * 0.70710678118654752f));
                }
                uint2 pk;
                pk.x = pack_bf2(v.x, v.y);
                pk.y = pack_bf2(v.z, v.w);
                *(uint2*)(crow_bf + col) = pk;
            } else {
                if (rrow) {
                    float4 r4 = *(const float4*)(rrow + col);
                    v.x += r4.x; v.y += r4.y; v.z += r4.z; v.w += r4.w;
                }
                *(float4*)(crow + col) = v;
            }
        }
    }
}

// ---------------------------------------------------------------------------
// Windowed attention, register-blocked SIMT fp32 compute, bf16 smem tiles
// (lossless: qkv already bf16), fp32 softmax probs. 2 CTAs/SM.
// q-scale folded post-accumulation: acc*SCALE + bias.
// ---------------------------------------------------------------------------
// smem (bytes): qsb 64*136*2 | ktb 128*72*2 | vsb 64*136*2 | at 64*65*4 | bt 240*4
#define ATTN_SMEM_BYTES (64*136*2 + 128*72*2 + 64*136*2 + 64*65*4 + 240*4)

__global__ __launch_bounds__(256, 2) void attn_kernel(
    const __nv_bfloat16* __restrict__ qkv, const float* __restrict__ bias_table,
    __nv_bfloat16* __restrict__ out)
{
    extern __shared__ __align__(16) char smc[];
    __nv_bfloat16* qsb = (__nv_bfloat16*)smc;        // [64][136]
    __nv_bfloat16* ktb = qsb + 64 * 136;             // [128][72]  ktb[d][m]
    __nv_bfloat16* vsb = ktb + 128 * 72;             // [64][136]
    float* at = (float*)(vsb + 64 * 136);            // [64][65]
    float* bt = at + 64 * 65;                        // 225 bias values

    const int wi   = blockIdx.x >> 2;
    const int head = blockIdx.x & 3;
    const int tid  = threadIdx.x;
    const float SCALE = 0.08838834764831845f;

    const __nv_bfloat16* base = qkv + (long)wi * 64 * 1536 + head * 128;
    for (int idx = tid; idx < 64 * 16; idx += 256) {
        int row = idx >> 4;
        int c   = (idx & 15) << 3;       // 0..120 step 8
        const __nv_bfloat16* p = base + (long)row * 1536 + c;
        uint4 qa = *(const uint4*)(p);
        uint4 ka = *(const uint4*)(p + 512);
        uint4 va = *(const uint4*)(p + 1024);
        *(uint4*)(qsb + row * 136 + c) = qa;
        *(uint4*)(vsb + row * 136 + c) = va;
        const uint32_t kw[4] = {ka.x, ka.y, ka.z, ka.w};
#pragma unroll
        for (int j = 0; j < 4; j++) {
            __nv_bfloat162 kp = *(const __nv_bfloat162*)&kw[j];
            int cc = c + 2 * j;
            ktb[(cc)     * 72 + row] = kp.x;
            ktb[(cc + 1) * 72 + row] = kp.y;
        }
    }
    if (tid < 225) bt[tid] = bias_table[tid];
    __syncthreads();

    const int rq = tid >> 4;      // 0..15
    const int cq = tid & 15;      // 0..15
    const int r0 = rq << 2;
    const int c0 = cq << 2;

    // ---- QK^T: 4 rows x 4 cols per thread (raw q, scale folded later) ----
    float acc[4][4];
#pragma unroll
    for (int i = 0; i < 4; i++)
#pragma unroll
        for (int j = 0; j < 4; j++) acc[i][j] = 0.0f;

#pragma unroll 2
    for (int d = 0; d < 128; d++) {
        float a0 = __bfloat162float(qsb[(r0 + 0) * 136 + d]);
        float a1 = __bfloat162float(qsb[(r0 + 1) * 136 + d]);
        float a2 = __bfloat162float(qsb[(r0 + 2) * 136 + d]);
        float a3 = __bfloat162float(qsb[(r0 + 3) * 136 + d]);
        uint2 bb = *(const uint2*)&ktb[d * 72 + c0];
        float2 b01 = __bfloat1622float2(*(const __nv_bfloat162*)&bb.x);
        float2 b23 = __bfloat1622float2(*(const __nv_bfloat162*)&bb.y);
        float b[4] = {b01.x, b01.y, b23.x, b23.y};
#pragma unroll
        for (int j = 0; j < 4; j++) {
            acc[0][j] = fmaf(a0, b[j], acc[0][j]);
            acc[1][j] = fmaf(a1, b[j], acc[1][j]);
            acc[2][j] = fmaf(a2, b[j], acc[2][j]);
            acc[3][j] = fmaf(a3, b[j], acc[3][j]);
        }
    }

    // ---- scale + bias + softmax (rows r0..r0+3, reduce across 16 lanes) ----
    float mx[4] = {-1e30f, -1e30f, -1e30f, -1e30f};
#pragma unroll
    for (int i = 0; i < 4; i++) {
        int r = r0 + i, ry = r >> 3, rx = r & 7;
#pragma unroll
        for (int j = 0; j < 4; j++) {
            int m = c0 + j;
            acc[i][j] = fmaf(acc[i][j], SCALE,
                             bt[(ry - (m >> 3) + 7) * 15 + (rx - (m & 7) + 7)]);
            mx[i] = fmaxf(mx[i], acc[i][j]);
        }
    }
#pragma unroll
    for (int o = 1; o < 16; o <<= 1)
#pragma unroll
        for (int i = 0; i < 4; i++)
            mx[i] = fmaxf(mx[i], __shfl_xor_sync(0xffffffffu, mx[i], o));
    float sum[4] = {0.f, 0.f, 0.f, 0.f};
#pragma unroll
    for (int i = 0; i < 4; i++)
#pragma unroll
        for (int j = 0; j < 4; j++) {
            acc[i][j] = __expf(acc[i][j] - mx[i]);
            sum[i] += acc[i][j];
        }
#pragma unroll
    for (int o = 1; o < 16; o <<= 1)
#pragma unroll
        for (int i = 0; i < 4; i++)
            sum[i] += __shfl_xor_sync(0xffffffffu, sum[i], o);
#pragma unroll
    for (int i = 0; i < 4; i++) {
        float inv = 1.0f / sum[i];
#pragma unroll
        for (int j = 0; j < 4; j++)
            at[(r0 + i) * 65 + c0 + j] = acc[i][j] * inv;
    }
    __syncwarp();

    // ---- attn @ V: 4 rows x 8 d per thread ----
    const int d0 = cq << 3;   // 0..120
    float o8[4][8];
#pragma unroll
    for (int i = 0; i < 4; i++)
#pragma unroll
        for (int j = 0; j < 8; j++) o8[i][j] = 0.0f;

    for (int m = 0; m < 64; m++) {
        float a0 = at[(r0 + 0) * 65 + m];
        float a1 = at[(r0 + 1) * 65 + m];
        float a2 = at[(r0 + 2) * 65 + m];
        float a3 = at[(r0 + 3) * 65 + m];
        uint4 vv4 = *(const uint4*)&vsb[m * 136 + d0];
        float2 f0 = __bfloat1622float2(*(const __nv_bfloat162*)&vv4.x);
        float2 f1 = __bfloat1622float2(*(const __nv_bfloat162*)&vv4.y);
        float2 f2 = __bfloat1622float2(*(const __nv_bfloat162*)&vv4.z);
        float2 f3 = __bfloat1622float2(*(const __nv_bfloat162*)&vv4.w);
        float vv[8] = {f0.x, f0.y, f1.x, f1.y, f2.x, f2.y, f3.x, f3.y};
#pragma unroll
        for (int j = 0; j < 8; j++) {
            o8[0][j] = fmaf(a0, vv[j], o8[0][j]);
            o8[1][j] = fmaf(a1, vv[j], o8[1][j]);
            o8[2][j] = fmaf(a2, vv[j], o8[2][j]);
            o8[3][j] = fmaf(a3, vv[j], o8[3][j]);
        }
    }
#pragma unroll
    for (int i = 0; i < 4; i++) {
        __nv_bfloat16* op = out + ((long)(wi * 64 + r0 + i)) * DIMC + head * 128 + d0;
        uint4 pk;
        pk.x = pack_bf2(o8[i][0], o8[i][1]);
        pk.y = pack_bf2(o8[i][2], o8[i][3]);
        pk.z = pack_bf2(o8[i][4], o8[i][5]);
        pk.w = pack_bf2(o8[i][6], o8[i][7]);
        *(uint4*)op = pk;
    }
}

// ---------------------------------------------------------------------------
extern "C" void kernel_launch(void* const* d_in, const int* in_sizes, int n_in,
                              void* d_out, int out_size)
{
    const float* x      = (const float*)d_in[0];
    const float* ln1_g  = (const float*)d_in[1];
    const float* ln1_b  = (const float*)d_in[2];
    const float* qkv_w  = (const float*)d_in[3];
    const float* qkv_b  = (const float*)d_in[4];
    const float* proj_w = (const float*)d_in[5];
    const float* proj_b = (const float*)d_in[6];
    const float* btab   = (const float*)d_in[7];
    const float* ln2_g  = (const float*)d_in[8];
    const float* ln2_b  = (const float*)d_in[9];
    const float* mlp_w1 = (const float*)d_in[10];
    const float* mlp_b1 = (const float*)d_in[11];
    const float* mlp_w2 = (const float*)d_in[12];
    const float* mlp_b2 = (const float*)d_in[13];
    float* outp = (float*)d_out;

    float* S = nullptr;
    cudaGetSymbolAddress((void**)&S, g_scratch);
    __nv_bfloat16* hw   = (__nv_bfloat16*)(S + OFF_HW);
    __nv_bfloat16* qkv  = (__nv_bfloat16*)(S + OFF_QKV);
    __nv_bfloat16* aout = (__nv_bfloat16*)(S + OFF_AOUT);
    float*         x2   = S + OFF_X2;
    __nv_bfloat16* h2n  = (__nv_bfloat16*)(S + OFF_H2N);
    __nv_bfloat16* m1   = (__nv_bfloat16*)(S + OFF_MLP1);
    __nv_bfloat16* wq   = (__nv_bfloat16*)(S + OFF_WQKV);
    __nv_bfloat16* wp   = (__nv_bfloat16*)(S + OFF_WPROJ);
    __nv_bfloat16* w1   = (__nv_bfloat16*)(S + OFF_WM1);
    __nv_bfloat16* w2   = (__nv_bfloat16*)(S + OFF_WM2);

    cudaFuncSetAttribute(attn_kernel, cudaFuncAttributeMaxDynamicSharedMemorySize,
                         ATTN_SMEM_BYTES);
    cudaFuncSetAttribute(mma_gemm, cudaFuncAttributeMaxDynamicSharedMemorySize,
                         GSMEM_BYTES);

    // transposed bf16 weights [N][K]
    transpose_kernel<<<dim3(48, 16), dim3(32, 8)>>>(qkv_w, wq, 512, 1536);
    transpose_kernel<<<dim3(16, 16), dim3(32, 8)>>>(proj_w, wp, 512, 512);
    transpose_kernel<<<dim3(64, 16), dim3(32, 8)>>>(mlp_w1, w1, 512, 2048);
    transpose_kernel<<<dim3(16, 64), dim3(32, 8)>>>(mlp_w2, w2, 2048, 512);

    // 1) LN1 + cyclic shift + window partition (bf16 out)
    ln_kernel<<<TOKENS / 8, 256>>>(x, ln1_g, ln1_b, hw, 1);
    // 2) QKV GEMM (bf16 out)
    mma_gemm<<<dim3(12, 512), 256, GSMEM_BYTES>>>(hw, wq, qkv_b, qkv,
                                                  512, 1536, 0, nullptr);
    // 3) windowed attention (bf16 out)
    attn_kernel<<<NWIN * 4, 256, ATTN_SMEM_BYTES>>>(qkv, btab, aout);
    // 4) proj + window reverse + unshift + residual(x) -> x2 (f32)
    mma_gemm<<<dim3(4, 512), 256, GSMEM_BYTES>>>(aout, wp, proj_b, x2,
                                                 512, 512, 1, x);
    // 5) LN2 (bf16 out)
    ln_kernel<<<TOKENS / 8, 256>>>(x2, ln2_g, ln2_b, h2n, 0);
    // 6) MLP1 + exact GELU (bf16 out)
    mma_gemm<<<dim3(16, 512), 256, GSMEM_BYTES>>>(h2n, w1, mlp_b1, m1,
                                                  512, 2048, 2, nullptr);
    // 7) MLP2 + residual(x2) -> output (f32)
    mma_gemm<<<dim3(4, 512), 256, GSMEM_BYTES>>>(m1, w2, mlp_b2, outp,
                                                 2048, 512, 3, x2);
}